// round 12
// baseline (speedup 1.0000x reference)
#include <cuda_runtime.h>
#include <cuda_fp16.h>
#include <cstdint>

// ---------------- problem constants ----------------
#define BATCH   256
#define NH      12
#define HD      64
#define DIM     768          // NH*HD
#define WIN     14
#define NTOK    196          // WIN*WIN
#define NPAD    256          // padded token count for K/V tiles
#define MTOT    (BATCH*NTOK) // 50176
#define REL     27           // 2*WIN-1

// ---------------- scratch (device globals; no allocation allowed) -------
__device__ float g_q[BATCH*NH*NTOK*HD];                      // fp32, q*0.125
__device__ __half g_kH[BATCH*NH*NPAD*HD], g_kL[BATCH*NH*NPAD*HD]; // [b][h][n][d] hi/lo
__device__ __half g_vH[BATCH*NH*HD*NPAD], g_vL[BATCH*NH*HD*NPAD]; // [b][h][d][n] hi/lo
__device__ __half g_xF[MTOT*DIM];                            // x single fp16
__device__ __half g_wqF[3*DIM*DIM];                          // qkv_w single fp16
__device__ __half g_wpF[DIM*DIM];                            // proj_w single fp16
__device__ __half g_aoF[MTOT*DIM];                           // attn out single fp16

// =========================================================================
// helpers
// =========================================================================
__device__ __forceinline__ void mma_f16(float c[4],
                                        uint32_t a0, uint32_t a1, uint32_t a2, uint32_t a3,
                                        uint32_t b0, uint32_t b1)
{
    asm("mma.sync.aligned.m16n8k16.row.col.f32.f16.f16.f32 "
        "{%0,%1,%2,%3}, {%4,%5,%6,%7}, {%8,%9}, {%0,%1,%2,%3};"
        : "+f"(c[0]), "+f"(c[1]), "+f"(c[2]), "+f"(c[3])
        : "r"(a0), "r"(a1), "r"(a2), "r"(a3), "r"(b0), "r"(b1));
}

__device__ __forceinline__ uint32_t pack_f16(float x0, float x1)
{
    uint32_t h;
    asm("cvt.rn.f16x2.f32 %0, %1, %2;" : "=r"(h) : "f"(x1), "f"(x0));
    return h;
}

// (x0,x1) -> f16x2 hi + f16x2 residual lo
__device__ __forceinline__ void pack_hl16(float x0, float x1, uint32_t& hi, uint32_t& lo)
{
    uint32_t h;
    asm("cvt.rn.f16x2.f32 %0, %1, %2;" : "=r"(h) : "f"(x1), "f"(x0));
    __half2 hh = *reinterpret_cast<__half2*>(&h);
    float h0 = __low2float(hh);
    float h1 = __high2float(hh);
    uint32_t l;
    asm("cvt.rn.f16x2.f32 %0, %1, %2;" : "=r"(l) : "f"(x1 - h1), "f"(x0 - h0));
    hi = h; lo = l;
}

__device__ __forceinline__ void cp16(uint32_t dst, const void* src)
{
    asm volatile("cp.async.cg.shared.global [%0], [%1], 16;" :: "r"(dst), "l"(src));
}
#define CP_COMMIT() asm volatile("cp.async.commit_group;")
#define CP_WAIT(n)  asm volatile("cp.async.wait_group %0;" :: "n"(n))

// =========================================================================
// one-shot fp32 -> single fp16 convert kernels
// =========================================================================
template<int WHICH>
__global__ __launch_bounds__(256) void split_kernel(const float* __restrict__ src, int n2)
{
    const int i = blockIdx.x * 256 + threadIdx.x;
    if (i >= n2) return;
    float2 v = ((const float2*)src)[i];
    uint32_t p = pack_f16(v.x, v.y);
    if (WHICH == 0)      ((uint32_t*)g_xF)[i]  = p;
    else if (WHICH == 1) ((uint32_t*)g_wqF)[i] = p;
    else                 ((uint32_t*)g_wpF)[i] = p;
}

// =========================================================================
// fp16 1-term GEMM: A single, B single. reg-prefetch double buffer.
// CTA tile 128x128, BK=32, 256 threads = 8 warps (2M x 4N), warp 64x32.
// MODE 0: x @ qkv_w -> q fp32 / k,v fp16 hi-lo scatter.  MODE 1: proj.
// =========================================================================
#define KSTR 40                       // fp16 smem row stride

template<int MODE>
__global__ __launch_bounds__(256) void gemm_mma(const float* __restrict__ bias,
                                                float* __restrict__ out)
{
    __shared__ __half AsF[128 * KSTR];
    __shared__ __half BsF[128 * KSTR];

    const int tid = threadIdx.x;
    const int m0  = blockIdx.y * 128;
    const int n0  = blockIdx.x * 128;

    const int w    = tid >> 5;
    const int lane = tid & 31;
    const int g    = lane >> 2;
    const int t    = lane & 3;
    const int wm   = (w >> 2) * 64;
    const int wn   = (w & 3) * 32;

    const int lr = tid >> 2;          // 0..63
    const int lc = (tid & 3) * 8;     // fp16 col 0,8,16,24

    const __half* gA = (MODE ? g_aoF : g_xF) + (size_t)(m0 + lr) * 768 + lc;
    const __half* gB = (MODE ? g_wpF : g_wqF) + (size_t)(n0 + lr) * 768 + lc;
    const size_t rstep = (size_t)64 * 768;

    float acc[4][4][4];
#pragma unroll
    for (int i = 0; i < 4; i++)
#pragma unroll
        for (int j = 0; j < 4; j++)
#pragma unroll
            for (int r = 0; r < 4; r++) acc[i][j][r] = 0.f;

    uint4 pa[2], pb[2];
    pa[0] = *(const uint4*)(gA);          pa[1] = *(const uint4*)(gA + rstep);
    pb[0] = *(const uint4*)(gB);          pb[1] = *(const uint4*)(gB + rstep);

    for (int k0 = 0; k0 < 768; k0 += 32) {
#pragma unroll
        for (int i = 0; i < 2; i++) {
            const int ro = (lr + i * 64) * KSTR + lc;
            *(uint4*)&AsF[ro] = pa[i];
            *(uint4*)&BsF[ro] = pb[i];
        }
        __syncthreads();

        if (k0 + 32 < 768) {
            const int k1 = k0 + 32;
            pa[0] = *(const uint4*)(gA + k1);          pa[1] = *(const uint4*)(gA + k1 + rstep);
            pb[0] = *(const uint4*)(gB + k1);          pb[1] = *(const uint4*)(gB + k1 + rstep);
        }

#pragma unroll
        for (int ks = 0; ks < 2; ks++) {
            const int kb = ks * 16 + 2 * t;
            uint32_t a[4][4], b[4][2];
#pragma unroll
            for (int mt = 0; mt < 4; mt++) {
                const int ro = (wm + mt * 16 + g) * KSTR + kb;
                a[mt][0] = *(const uint32_t*)&AsF[ro];
                a[mt][1] = *(const uint32_t*)&AsF[ro + 8 * KSTR];
                a[mt][2] = *(const uint32_t*)&AsF[ro + 8];
                a[mt][3] = *(const uint32_t*)&AsF[ro + 8 * KSTR + 8];
            }
#pragma unroll
            for (int nt = 0; nt < 4; nt++) {
                const int ro = (wn + nt * 8 + g) * KSTR + kb;
                b[nt][0] = *(const uint32_t*)&BsF[ro];
                b[nt][1] = *(const uint32_t*)&BsF[ro + 8];
            }
#pragma unroll
            for (int mt = 0; mt < 4; mt++)
#pragma unroll
                for (int nt = 0; nt < 4; nt++)
                    mma_f16(acc[mt][nt], a[mt][0], a[mt][1], a[mt][2], a[mt][3],
                            b[nt][0], b[nt][1]);
        }
        __syncthreads();
    }

    // ----- epilogue -----
#pragma unroll
    for (int mt = 0; mt < 4; mt++) {
#pragma unroll
        for (int half = 0; half < 2; half++) {
            const int m = m0 + wm + mt * 16 + g + half * 8;
            if (MODE == 0) {
                const int b = m / NTOK;
                const int n = m - b * NTOK;
#pragma unroll
                for (int nt = 0; nt < 4; nt++) {
                    const int col0 = n0 + wn + nt * 8 + 2 * t;
                    float v0 = acc[mt][nt][half * 2 + 0] + bias[col0];
                    float v1 = acc[mt][nt][half * 2 + 1] + bias[col0 + 1];
                    const int which = col0 / DIM;
                    const int rem   = col0 - which * DIM;
                    const int h     = rem >> 6;
                    const int dd    = rem & 63;
                    const int bhI   = b * NH + h;
                    if (which == 0) {
                        float2 q2 = make_float2(v0 * 0.125f, v1 * 0.125f);
                        *(float2*)&g_q[((size_t)bhI * NTOK + n) * HD + dd] = q2;
                    } else if (which == 1) {
                        uint32_t hp, lp;
                        pack_hl16(v0, v1, hp, lp);
                        const size_t idx = ((size_t)bhI * NPAD + n) * HD + dd;
                        *(uint32_t*)&g_kH[idx] = hp;
                        *(uint32_t*)&g_kL[idx] = lp;
                    } else { // V transposed [d][n], hi/lo
                        const size_t i0 = ((size_t)bhI * HD + dd) * NPAD + n;
                        __half h0 = __float2half_rn(v0);
                        __half h1 = __float2half_rn(v1);
                        g_vH[i0]        = h0;
                        g_vH[i0 + NPAD] = h1;
                        g_vL[i0]        = __float2half_rn(v0 - __half2float(h0));
                        g_vL[i0 + NPAD] = __float2half_rn(v1 - __half2float(h1));
                    }
                }
            } else {
#pragma unroll
                for (int nt = 0; nt < 4; nt++) {
                    const int col = n0 + wn + nt * 8 + 2 * t;
                    float2 v;
                    v.x = acc[mt][nt][half * 2 + 0] + bias[col];
                    v.y = acc[mt][nt][half * 2 + 1] + bias[col + 1];
                    *(float2*)&out[(size_t)m * DIM + col] = v;
                }
            }
        }
    }
}

// =========================================================================
// Tensor-core flash attention (unchanged from round 11):
// Q single fp16, K hi/lo, P single, V hi/lo. One CTA per (b,h),
// 416 threads = 13 warps, cp.async double buffer.
// =========================================================================
#define KS_STR  72
#define KV_TILE (64*KS_STR*2)
#define KV_STAGE (4*KV_TILE)
#define SRH_OFF 0
#define SRW_OFF (SRH_OFF + REL*HD*4)
#define SBH_OFF (SRW_OFF + REL*HD*4)
#define SBW_OFF (SBH_OFF + 208*14*4)
#define SKV_OFF (SBW_OFF + 208*14*4)
#define ATT_SMEM (SKV_OFF + 2*KV_STAGE)           // 110848 B

#define ATHR 416

__global__ __launch_bounds__(ATHR, 1) void attn_mma(const float* __restrict__ relh,
                                                    const float* __restrict__ relw)
{
    extern __shared__ char smc[];
    float* RH = (float*)(smc + SRH_OFF);
    float* RW = (float*)(smc + SRW_OFF);
    float* BH = (float*)(smc + SBH_OFF);
    float* BW = (float*)(smc + SBW_OFF);

    const int bh  = blockIdx.x;
    const int tid = threadIdx.x;
    const int w    = tid >> 5;
    const int lane = tid & 31;
    const int g    = lane >> 2;
    const int t    = lane & 3;

    const float* qg = g_q + (size_t)bh * NTOK * HD;
    const uint32_t kvbase = (uint32_t)__cvta_generic_to_shared(smc + SKV_OFF);

#define PREFETCH_CHUNK(j0, s)                                              \
    {                                                                      \
        for (int idx = tid; idx < 2048; idx += ATHR) {                     \
            const int tile = idx >> 9;                                     \
            const int r    = (idx >> 3) & 63;                              \
            const int c8   = idx & 7;                                      \
            const __half* src;                                             \
            if (tile == 0)      src = g_kH + ((size_t)bh * NPAD + (j0) + r) * HD + c8 * 8; \
            else if (tile == 1) src = g_kL + ((size_t)bh * NPAD + (j0) + r) * HD + c8 * 8; \
            else if (tile == 2) src = g_vH + ((size_t)bh * HD + r) * NPAD + (j0) + c8 * 8; \
            else                src = g_vL + ((size_t)bh * HD + r) * NPAD + (j0) + c8 * 8; \
            cp16(kvbase + (s) * KV_STAGE + tile * KV_TILE + r * (KS_STR*2) + c8 * 16, src); \
        }                                                                  \
        CP_COMMIT();                                                       \
    }

    PREFETCH_CHUNK(0, 0);

    for (int idx = tid; idx < REL * HD / 4; idx += ATHR) {
        ((float4*)RH)[idx] = ((const float4*)relh)[idx];
        ((float4*)RW)[idx] = ((const float4*)relw)[idx];
    }
    __syncthreads();

    if (tid < NTOK) {
        float4 q4[16];
        const float4* qr = (const float4*)(qg + tid * HD);
#pragma unroll
        for (int i = 0; i < 16; i++) q4[i] = qr[i];
        const int qh = tid / WIN, qw = tid - qh * WIN;
#pragma unroll 1
        for (int kk = 0; kk < WIN; kk++) {
            const float4* rh4 = (const float4*)(RH + (qh - kk + WIN - 1) * HD);
            const float4* rw4 = (const float4*)(RW + (qw - kk + WIN - 1) * HD);
            float sh = 0.f, sw = 0.f;
#pragma unroll
            for (int i = 0; i < 16; i++) {
                float4 a = q4[i], r = rh4[i], wv = rw4[i];
                sh += a.x * r.x + a.y * r.y + a.z * r.z + a.w * r.w;
                sw += a.x * wv.x + a.y * wv.y + a.z * wv.z + a.w * wv.w;
            }
            BH[tid * WIN + kk] = sh;
            BW[tid * WIN + kk] = sw;
        }
    } else if (tid < 208) {
#pragma unroll
        for (int kk = 0; kk < WIN; kk++) {
            BH[tid * WIN + kk] = 0.f;
            BW[tid * WIN + kk] = 0.f;
        }
    }

    // Q fragments: single fp16
    const int r0 = w * 16 + g;
    const int r1 = r0 + 8;
    const int rq0 = (r0 < NTOK) ? r0 : NTOK - 1;
    const int rq1 = (r1 < NTOK) ? r1 : NTOK - 1;
    uint32_t qf[4][4];
#pragma unroll
    for (int kt = 0; kt < 4; kt++) {
        const int kc = kt * 16 + 2 * t;
        float2 v0 = *(const float2*)(qg + rq0 * HD + kc);
        float2 v1 = *(const float2*)(qg + rq1 * HD + kc);
        float2 v2 = *(const float2*)(qg + rq0 * HD + kc + 8);
        float2 v3 = *(const float2*)(qg + rq1 * HD + kc + 8);
        qf[kt][0] = pack_f16(v0.x, v0.y);
        qf[kt][1] = pack_f16(v1.x, v1.y);
        qf[kt][2] = pack_f16(v2.x, v2.y);
        qf[kt][3] = pack_f16(v3.x, v3.y);
    }

    float oacc[8][4];
#pragma unroll
    for (int j = 0; j < 8; j++)
#pragma unroll
        for (int r = 0; r < 4; r++) oacc[j][r] = 0.f;
    float lsum0 = 0.f, lsum1 = 0.f;

#pragma unroll 1
    for (int chunk = 0; chunk < 4; chunk++) {
        const int j0 = chunk * 64;
        const int s  = chunk & 1;
        CP_WAIT(0);
        __syncthreads();
        if (chunk < 3) PREFETCH_CHUNK(j0 + 64, s ^ 1);

        const __half* KH = (const __half*)(smc + SKV_OFF + s * KV_STAGE);
        const __half* KL = KH + 64 * KS_STR;
        const __half* VH = KH + 2 * 64 * KS_STR;
        const __half* VL = KH + 3 * 64 * KS_STR;

        float sacc[8][4];
#pragma unroll
        for (int j = 0; j < 8; j++)
#pragma unroll
            for (int r = 0; r < 4; r++) sacc[j][r] = 0.f;

#pragma unroll
        for (int kt = 0; kt < 4; kt++) {
            const int kc = kt * 16 + 2 * t;
#pragma unroll
            for (int nt = 0; nt < 8; nt++) {
                const int krow = (nt * 8 + g) * KS_STR + kc;
                uint32_t kh0 = *(const uint32_t*)&KH[krow];
                uint32_t kh1 = *(const uint32_t*)&KH[krow + 8];
                uint32_t kl0 = *(const uint32_t*)&KL[krow];
                uint32_t kl1 = *(const uint32_t*)&KL[krow + 8];
                mma_f16(sacc[nt], qf[kt][0], qf[kt][1], qf[kt][2], qf[kt][3], kl0, kl1);
                mma_f16(sacc[nt], qf[kt][0], qf[kt][1], qf[kt][2], qf[kt][3], kh0, kh1);
            }
        }

#pragma unroll
        for (int nt = 0; nt < 8; nt++) {
#pragma unroll
            for (int e = 0; e < 2; e++) {
                const int c = j0 + nt * 8 + 2 * t + e;
                float p0 = 0.f, p1 = 0.f;
                if (c < NTOK) {
                    const int kh = c / WIN;
                    const int kw = c - kh * WIN;
                    p0 = __expf(sacc[nt][e]     + BH[r0 * WIN + kh] + BW[r0 * WIN + kw]);
                    p1 = __expf(sacc[nt][2 + e] + BH[r1 * WIN + kh] + BW[r1 * WIN + kw]);
                }
                sacc[nt][e]     = p0;
                sacc[nt][2 + e] = p1;
                lsum0 += p0;
                lsum1 += p1;
            }
        }

#pragma unroll
        for (int kt = 0; kt < 4; kt++) {
            uint32_t ph[4];
            ph[0] = pack_f16(sacc[2*kt][0],   sacc[2*kt][1]);
            ph[1] = pack_f16(sacc[2*kt][2],   sacc[2*kt][3]);
            ph[2] = pack_f16(sacc[2*kt+1][0], sacc[2*kt+1][1]);
            ph[3] = pack_f16(sacc[2*kt+1][2], sacc[2*kt+1][3]);
            const int kc = kt * 16 + 2 * t;
#pragma unroll
            for (int nt = 0; nt < 8; nt++) {
                const int vrow = (nt * 8 + g) * KS_STR + kc;
                uint32_t vh0 = *(const uint32_t*)&VH[vrow];
                uint32_t vh1 = *(const uint32_t*)&VH[vrow + 8];
                uint32_t vl0 = *(const uint32_t*)&VL[vrow];
                uint32_t vl1 = *(const uint32_t*)&VL[vrow + 8];
                mma_f16(oacc[nt], ph[0], ph[1], ph[2], ph[3], vl0, vl1);
                mma_f16(oacc[nt], ph[0], ph[1], ph[2], ph[3], vh0, vh1);
            }
        }
    }

    lsum0 += __shfl_xor_sync(0xffffffff, lsum0, 1);
    lsum0 += __shfl_xor_sync(0xffffffff, lsum0, 2);
    lsum1 += __shfl_xor_sync(0xffffffff, lsum1, 1);
    lsum1 += __shfl_xor_sync(0xffffffff, lsum1, 2);

    const int b = bh / NH, h = bh - (bh / NH) * NH;
    const float inv0 = 1.f / lsum0;
    const float inv1 = 1.f / lsum1;
    if (r0 < NTOK) {
        const size_t off = ((size_t)b * NTOK + r0) * DIM + h * HD;
#pragma unroll
        for (int nt = 0; nt < 8; nt++)
            *(uint32_t*)&g_aoF[off + nt * 8 + 2 * t] =
                pack_f16(oacc[nt][0] * inv0, oacc[nt][1] * inv0);
    }
    if (r1 < NTOK) {
        const size_t off = ((size_t)b * NTOK + r1) * DIM + h * HD;
#pragma unroll
        for (int nt = 0; nt < 8; nt++)
            *(uint32_t*)&g_aoF[off + nt * 8 + 2 * t] =
                pack_f16(oacc[nt][2] * inv1, oacc[nt][3] * inv1);
    }
}

// =========================================================================
extern "C" void kernel_launch(void* const* d_in, const int* in_sizes, int n_in,
                              void* d_out, int out_size)
{
    const float* x      = (const float*)d_in[0];
    const float* qkv_w  = (const float*)d_in[1];
    const float* qkv_b  = (const float*)d_in[2];
    const float* relh   = (const float*)d_in[3];
    const float* relw   = (const float*)d_in[4];
    const float* proj_w = (const float*)d_in[5];
    const float* proj_b = (const float*)d_in[6];
    float* out = (float*)d_out;

    cudaFuncSetAttribute(attn_mma,
                         cudaFuncAttributeMaxDynamicSharedMemorySize, ATT_SMEM);

    // 0) one-shot fp16 converts
    {
        const int n2x = MTOT * DIM / 2;
        split_kernel<0><<<(n2x + 255) / 256, 256>>>(x, n2x);
        const int n2q = 3 * DIM * DIM / 2;
        split_kernel<1><<<(n2q + 255) / 256, 256>>>(qkv_w, n2q);
        const int n2p = DIM * DIM / 2;
        split_kernel<2><<<(n2p + 255) / 256, 256>>>(proj_w, n2p);
    }

    // 1) QKV GEMM (1-term) -> g_q (fp32), g_k hi/lo, g_v hi/lo transposed
    gemm_mma<0><<<dim3(2304 / 128, MTOT / 128), 256>>>(qkv_b, nullptr);

    // 2) tensor-core flash attention per (b, head) -> g_aoF
    attn_mma<<<BATCH * NH, ATHR, ATT_SMEM>>>(relh, relw);

    // 3) proj GEMM (1-term) -> d_out
    gemm_mma<1><<<dim3(DIM / 128, MTOT / 128), 256>>>(proj_b, out);
}

// round 13
// speedup vs baseline: 1.5750x; 1.5750x over previous
#include <cuda_runtime.h>
#include <cuda_fp16.h>
#include <cstdint>

// ---------------- problem constants ----------------
#define BATCH   256
#define NH      12
#define HD      64
#define DIM     768          // NH*HD
#define WIN     14
#define NTOK    196          // WIN*WIN
#define NPAD    256          // padded token count for K/V tiles
#define MTOT    (BATCH*NTOK) // 50176
#define REL     27           // 2*WIN-1

// ---------------- scratch (device globals; no allocation allowed) -------
__device__ float g_q[BATCH*NH*NTOK*HD];                      // fp32, q*0.125
__device__ __half g_kH[BATCH*NH*NPAD*HD], g_kL[BATCH*NH*NPAD*HD]; // [b][h][n][d] hi/lo
__device__ __half g_vH[BATCH*NH*HD*NPAD], g_vL[BATCH*NH*HD*NPAD]; // [b][h][d][n] hi/lo
__device__ __half g_xF[MTOT*DIM];                            // x single fp16
__device__ __half g_wqF[3*DIM*DIM];                          // qkv_w single fp16
__device__ __half g_wpF[DIM*DIM];                            // proj_w single fp16
__device__ __half g_aoF[MTOT*DIM];                           // attn out single fp16

// =========================================================================
// helpers
// =========================================================================
__device__ __forceinline__ void mma_f16(float c[4],
                                        uint32_t a0, uint32_t a1, uint32_t a2, uint32_t a3,
                                        uint32_t b0, uint32_t b1)
{
    asm("mma.sync.aligned.m16n8k16.row.col.f32.f16.f16.f32 "
        "{%0,%1,%2,%3}, {%4,%5,%6,%7}, {%8,%9}, {%0,%1,%2,%3};"
        : "+f"(c[0]), "+f"(c[1]), "+f"(c[2]), "+f"(c[3])
        : "r"(a0), "r"(a1), "r"(a2), "r"(a3), "r"(b0), "r"(b1));
}

__device__ __forceinline__ uint32_t pack_f16(float x0, float x1)
{
    uint32_t h;
    asm("cvt.rn.f16x2.f32 %0, %1, %2;" : "=r"(h) : "f"(x1), "f"(x0));
    return h;
}

// (x0,x1) -> f16x2 hi + f16x2 residual lo
__device__ __forceinline__ void pack_hl16(float x0, float x1, uint32_t& hi, uint32_t& lo)
{
    uint32_t h;
    asm("cvt.rn.f16x2.f32 %0, %1, %2;" : "=r"(h) : "f"(x1), "f"(x0));
    __half2 hh = *reinterpret_cast<__half2*>(&h);
    float h0 = __low2float(hh);
    float h1 = __high2float(hh);
    uint32_t l;
    asm("cvt.rn.f16x2.f32 %0, %1, %2;" : "=r"(l) : "f"(x1 - h1), "f"(x0 - h0));
    hi = h; lo = l;
}

__device__ __forceinline__ void cp16(uint32_t dst, const void* src)
{
    asm volatile("cp.async.cg.shared.global [%0], [%1], 16;" :: "r"(dst), "l"(src));
}
#define CP_COMMIT() asm volatile("cp.async.commit_group;")
#define CP_WAIT(n)  asm volatile("cp.async.wait_group %0;" :: "n"(n))

// =========================================================================
// one-shot fp32 -> single fp16 convert kernels
// =========================================================================
template<int WHICH>
__global__ __launch_bounds__(256) void split_kernel(const float* __restrict__ src, int n2)
{
    const int i = blockIdx.x * 256 + threadIdx.x;
    if (i >= n2) return;
    float2 v = ((const float2*)src)[i];
    uint32_t p = pack_f16(v.x, v.y);
    if (WHICH == 0)      ((uint32_t*)g_xF)[i]  = p;
    else if (WHICH == 1) ((uint32_t*)g_wqF)[i] = p;
    else                 ((uint32_t*)g_wpF)[i] = p;
}

// =========================================================================
// fp16 1-term GEMM, double-buffered smem, ONE sync per iteration.
// CTA tile 128x128, BK=32, 256 threads = 8 warps (2M x 4N), warp 64x32.
// MODE 0: x @ qkv_w -> q fp32 / k,v fp16 hi-lo scatter.  MODE 1: proj.
// =========================================================================
#define KSTR 40                       // fp16 smem row stride

template<int MODE>
__global__ __launch_bounds__(256) void gemm_mma(const float* __restrict__ bias,
                                                float* __restrict__ out)
{
    __shared__ __half AsF[2][128 * KSTR];
    __shared__ __half BsF[2][128 * KSTR];

    const int tid = threadIdx.x;
    const int m0  = blockIdx.y * 128;
    const int n0  = blockIdx.x * 128;

    const int w    = tid >> 5;
    const int lane = tid & 31;
    const int g    = lane >> 2;
    const int t    = lane & 3;
    const int wm   = (w >> 2) * 64;
    const int wn   = (w & 3) * 32;

    const int lr = tid >> 2;          // 0..63
    const int lc = (tid & 3) * 8;     // fp16 col 0,8,16,24
    const int ro0 = lr * KSTR + lc;

    const __half* gA = (MODE ? g_aoF : g_xF) + (size_t)(m0 + lr) * 768 + lc;
    const __half* gB = (MODE ? g_wpF : g_wqF) + (size_t)(n0 + lr) * 768 + lc;
    const size_t rstep = (size_t)64 * 768;

    float acc[4][4][4];
#pragma unroll
    for (int i = 0; i < 4; i++)
#pragma unroll
        for (int j = 0; j < 4; j++)
#pragma unroll
            for (int r = 0; r < 4; r++) acc[i][j][r] = 0.f;

    uint4 pa[2], pb[2];
    pa[0] = *(const uint4*)(gA);          pa[1] = *(const uint4*)(gA + rstep);
    pb[0] = *(const uint4*)(gB);          pb[1] = *(const uint4*)(gB + rstep);
    *(uint4*)&AsF[0][ro0]             = pa[0];
    *(uint4*)&AsF[0][ro0 + 64 * KSTR] = pa[1];
    *(uint4*)&BsF[0][ro0]             = pb[0];
    *(uint4*)&BsF[0][ro0 + 64 * KSTR] = pb[1];
    __syncthreads();

    for (int i = 0; i < 24; i++) {
        const int cur = i & 1;
        const bool more = (i + 1 < 24);

        // issue LDG prefetch early — latency hidden under compute
        if (more) {
            const int k1 = (i + 1) * 32;
            pa[0] = *(const uint4*)(gA + k1);          pa[1] = *(const uint4*)(gA + k1 + rstep);
            pb[0] = *(const uint4*)(gB + k1);          pb[1] = *(const uint4*)(gB + k1 + rstep);
        }

        // compute from stage cur
        const __half* As = AsF[cur];
        const __half* Bs = BsF[cur];
#pragma unroll
        for (int ks = 0; ks < 2; ks++) {
            const int kb = ks * 16 + 2 * t;
            uint32_t a[4][4], b[4][2];
#pragma unroll
            for (int mt = 0; mt < 4; mt++) {
                const int ro = (wm + mt * 16 + g) * KSTR + kb;
                a[mt][0] = *(const uint32_t*)&As[ro];
                a[mt][1] = *(const uint32_t*)&As[ro + 8 * KSTR];
                a[mt][2] = *(const uint32_t*)&As[ro + 8];
                a[mt][3] = *(const uint32_t*)&As[ro + 8 * KSTR + 8];
            }
#pragma unroll
            for (int nt = 0; nt < 4; nt++) {
                const int ro = (wn + nt * 8 + g) * KSTR + kb;
                b[nt][0] = *(const uint32_t*)&Bs[ro];
                b[nt][1] = *(const uint32_t*)&Bs[ro + 8];
            }
#pragma unroll
            for (int mt = 0; mt < 4; mt++)
#pragma unroll
                for (int nt = 0; nt < 4; nt++)
                    mma_f16(acc[mt][nt], a[mt][0], a[mt][1], a[mt][2], a[mt][3],
                            b[nt][0], b[nt][1]);
        }

        // store prefetched tile into the other stage (read finished at i-1's sync)
        if (more) {
            const int nxt = cur ^ 1;
            *(uint4*)&AsF[nxt][ro0]             = pa[0];
            *(uint4*)&AsF[nxt][ro0 + 64 * KSTR] = pa[1];
            *(uint4*)&BsF[nxt][ro0]             = pb[0];
            *(uint4*)&BsF[nxt][ro0 + 64 * KSTR] = pb[1];
        }
        __syncthreads();
    }

    // ----- epilogue -----
#pragma unroll
    for (int mt = 0; mt < 4; mt++) {
#pragma unroll
        for (int half = 0; half < 2; half++) {
            const int m = m0 + wm + mt * 16 + g + half * 8;
            if (MODE == 0) {
                const int b = m / NTOK;
                const int n = m - b * NTOK;
#pragma unroll
                for (int nt = 0; nt < 4; nt++) {
                    const int col0 = n0 + wn + nt * 8 + 2 * t;
                    float v0 = acc[mt][nt][half * 2 + 0] + bias[col0];
                    float v1 = acc[mt][nt][half * 2 + 1] + bias[col0 + 1];
                    const int which = col0 / DIM;
                    const int rem   = col0 - which * DIM;
                    const int h     = rem >> 6;
                    const int dd    = rem & 63;
                    const int bhI   = b * NH + h;
                    if (which == 0) {
                        float2 q2 = make_float2(v0 * 0.125f, v1 * 0.125f);
                        *(float2*)&g_q[((size_t)bhI * NTOK + n) * HD + dd] = q2;
                    } else if (which == 1) {
                        uint32_t hp, lp;
                        pack_hl16(v0, v1, hp, lp);
                        const size_t idx = ((size_t)bhI * NPAD + n) * HD + dd;
                        *(uint32_t*)&g_kH[idx] = hp;
                        *(uint32_t*)&g_kL[idx] = lp;
                    } else { // V transposed [d][n], hi/lo
                        const size_t i0 = ((size_t)bhI * HD + dd) * NPAD + n;
                        __half h0 = __float2half_rn(v0);
                        __half h1 = __float2half_rn(v1);
                        g_vH[i0]        = h0;
                        g_vH[i0 + NPAD] = h1;
                        g_vL[i0]        = __float2half_rn(v0 - __half2float(h0));
                        g_vL[i0 + NPAD] = __float2half_rn(v1 - __half2float(h1));
                    }
                }
            } else {
#pragma unroll
                for (int nt = 0; nt < 4; nt++) {
                    const int col = n0 + wn + nt * 8 + 2 * t;
                    float2 v;
                    v.x = acc[mt][nt][half * 2 + 0] + bias[col];
                    v.y = acc[mt][nt][half * 2 + 1] + bias[col + 1];
                    *(float2*)&out[(size_t)m * DIM + col] = v;
                }
            }
        }
    }
}

// =========================================================================
// Tensor-core flash attention (unchanged, proven):
// Q single fp16, K hi/lo, P single, V hi/lo. One CTA per (b,h),
// 416 threads = 13 warps, cp.async double buffer.
// =========================================================================
#define KS_STR  72
#define KV_TILE (64*KS_STR*2)
#define KV_STAGE (4*KV_TILE)
#define SRH_OFF 0
#define SRW_OFF (SRH_OFF + REL*HD*4)
#define SBH_OFF (SRW_OFF + REL*HD*4)
#define SBW_OFF (SBH_OFF + 208*14*4)
#define SKV_OFF (SBW_OFF + 208*14*4)
#define ATT_SMEM (SKV_OFF + 2*KV_STAGE)           // 110848 B

#define ATHR 416

__global__ __launch_bounds__(ATHR, 1) void attn_mma(const float* __restrict__ relh,
                                                    const float* __restrict__ relw)
{
    extern __shared__ char smc[];
    float* RH = (float*)(smc + SRH_OFF);
    float* RW = (float*)(smc + SRW_OFF);
    float* BH = (float*)(smc + SBH_OFF);
    float* BW = (float*)(smc + SBW_OFF);

    const int bh  = blockIdx.x;
    const int tid = threadIdx.x;
    const int w    = tid >> 5;
    const int lane = tid & 31;
    const int g    = lane >> 2;
    const int t    = lane & 3;

    const float* qg = g_q + (size_t)bh * NTOK * HD;
    const uint32_t kvbase = (uint32_t)__cvta_generic_to_shared(smc + SKV_OFF);

#define PREFETCH_CHUNK(j0, s)                                              \
    {                                                                      \
        for (int idx = tid; idx < 2048; idx += ATHR) {                     \
            const int tile = idx >> 9;                                     \
            const int r    = (idx >> 3) & 63;                              \
            const int c8   = idx & 7;                                      \
            const __half* src;                                             \
            if (tile == 0)      src = g_kH + ((size_t)bh * NPAD + (j0) + r) * HD + c8 * 8; \
            else if (tile == 1) src = g_kL + ((size_t)bh * NPAD + (j0) + r) * HD + c8 * 8; \
            else if (tile == 2) src = g_vH + ((size_t)bh * HD + r) * NPAD + (j0) + c8 * 8; \
            else                src = g_vL + ((size_t)bh * HD + r) * NPAD + (j0) + c8 * 8; \
            cp16(kvbase + (s) * KV_STAGE + tile * KV_TILE + r * (KS_STR*2) + c8 * 16, src); \
        }                                                                  \
        CP_COMMIT();                                                       \
    }

    PREFETCH_CHUNK(0, 0);

    for (int idx = tid; idx < REL * HD / 4; idx += ATHR) {
        ((float4*)RH)[idx] = ((const float4*)relh)[idx];
        ((float4*)RW)[idx] = ((const float4*)relw)[idx];
    }
    __syncthreads();

    if (tid < NTOK) {
        float4 q4[16];
        const float4* qr = (const float4*)(qg + tid * HD);
#pragma unroll
        for (int i = 0; i < 16; i++) q4[i] = qr[i];
        const int qh = tid / WIN, qw = tid - qh * WIN;
#pragma unroll 1
        for (int kk = 0; kk < WIN; kk++) {
            const float4* rh4 = (const float4*)(RH + (qh - kk + WIN - 1) * HD);
            const float4* rw4 = (const float4*)(RW + (qw - kk + WIN - 1) * HD);
            float sh = 0.f, sw = 0.f;
#pragma unroll
            for (int i = 0; i < 16; i++) {
                float4 a = q4[i], r = rh4[i], wv = rw4[i];
                sh += a.x * r.x + a.y * r.y + a.z * r.z + a.w * r.w;
                sw += a.x * wv.x + a.y * wv.y + a.z * wv.z + a.w * wv.w;
            }
            BH[tid * WIN + kk] = sh;
            BW[tid * WIN + kk] = sw;
        }
    } else if (tid < 208) {
#pragma unroll
        for (int kk = 0; kk < WIN; kk++) {
            BH[tid * WIN + kk] = 0.f;
            BW[tid * WIN + kk] = 0.f;
        }
    }

    // Q fragments: single fp16
    const int r0 = w * 16 + g;
    const int r1 = r0 + 8;
    const int rq0 = (r0 < NTOK) ? r0 : NTOK - 1;
    const int rq1 = (r1 < NTOK) ? r1 : NTOK - 1;
    uint32_t qf[4][4];
#pragma unroll
    for (int kt = 0; kt < 4; kt++) {
        const int kc = kt * 16 + 2 * t;
        float2 v0 = *(const float2*)(qg + rq0 * HD + kc);
        float2 v1 = *(const float2*)(qg + rq1 * HD + kc);
        float2 v2 = *(const float2*)(qg + rq0 * HD + kc + 8);
        float2 v3 = *(const float2*)(qg + rq1 * HD + kc + 8);
        qf[kt][0] = pack_f16(v0.x, v0.y);
        qf[kt][1] = pack_f16(v1.x, v1.y);
        qf[kt][2] = pack_f16(v2.x, v2.y);
        qf[kt][3] = pack_f16(v3.x, v3.y);
    }

    float oacc[8][4];
#pragma unroll
    for (int j = 0; j < 8; j++)
#pragma unroll
        for (int r = 0; r < 4; r++) oacc[j][r] = 0.f;
    float lsum0 = 0.f, lsum1 = 0.f;

#pragma unroll 1
    for (int chunk = 0; chunk < 4; chunk++) {
        const int j0 = chunk * 64;
        const int s  = chunk & 1;
        CP_WAIT(0);
        __syncthreads();
        if (chunk < 3) PREFETCH_CHUNK(j0 + 64, s ^ 1);

        const __half* KH = (const __half*)(smc + SKV_OFF + s * KV_STAGE);
        const __half* KL = KH + 64 * KS_STR;
        const __half* VH = KH + 2 * 64 * KS_STR;
        const __half* VL = KH + 3 * 64 * KS_STR;

        float sacc[8][4];
#pragma unroll
        for (int j = 0; j < 8; j++)
#pragma unroll
            for (int r = 0; r < 4; r++) sacc[j][r] = 0.f;

#pragma unroll
        for (int kt = 0; kt < 4; kt++) {
            const int kc = kt * 16 + 2 * t;
#pragma unroll
            for (int nt = 0; nt < 8; nt++) {
                const int krow = (nt * 8 + g) * KS_STR + kc;
                uint32_t kh0 = *(const uint32_t*)&KH[krow];
                uint32_t kh1 = *(const uint32_t*)&KH[krow + 8];
                uint32_t kl0 = *(const uint32_t*)&KL[krow];
                uint32_t kl1 = *(const uint32_t*)&KL[krow + 8];
                mma_f16(sacc[nt], qf[kt][0], qf[kt][1], qf[kt][2], qf[kt][3], kl0, kl1);
                mma_f16(sacc[nt], qf[kt][0], qf[kt][1], qf[kt][2], qf[kt][3], kh0, kh1);
            }
        }

#pragma unroll
        for (int nt = 0; nt < 8; nt++) {
#pragma unroll
            for (int e = 0; e < 2; e++) {
                const int c = j0 + nt * 8 + 2 * t + e;
                float p0 = 0.f, p1 = 0.f;
                if (c < NTOK) {
                    const int kh = c / WIN;
                    const int kw = c - kh * WIN;
                    p0 = __expf(sacc[nt][e]     + BH[r0 * WIN + kh] + BW[r0 * WIN + kw]);
                    p1 = __expf(sacc[nt][2 + e] + BH[r1 * WIN + kh] + BW[r1 * WIN + kw]);
                }
                sacc[nt][e]     = p0;
                sacc[nt][2 + e] = p1;
                lsum0 += p0;
                lsum1 += p1;
            }
        }

#pragma unroll
        for (int kt = 0; kt < 4; kt++) {
            uint32_t ph[4];
            ph[0] = pack_f16(sacc[2*kt][0],   sacc[2*kt][1]);
            ph[1] = pack_f16(sacc[2*kt][2],   sacc[2*kt][3]);
            ph[2] = pack_f16(sacc[2*kt+1][0], sacc[2*kt+1][1]);
            ph[3] = pack_f16(sacc[2*kt+1][2], sacc[2*kt+1][3]);
            const int kc = kt * 16 + 2 * t;
#pragma unroll
            for (int nt = 0; nt < 8; nt++) {
                const int vrow = (nt * 8 + g) * KS_STR + kc;
                uint32_t vh0 = *(const uint32_t*)&VH[vrow];
                uint32_t vh1 = *(const uint32_t*)&VH[vrow + 8];
                uint32_t vl0 = *(const uint32_t*)&VL[vrow];
                uint32_t vl1 = *(const uint32_t*)&VL[vrow + 8];
                mma_f16(oacc[nt], ph[0], ph[1], ph[2], ph[3], vl0, vl1);
                mma_f16(oacc[nt], ph[0], ph[1], ph[2], ph[3], vh0, vh1);
            }
        }
    }

    lsum0 += __shfl_xor_sync(0xffffffff, lsum0, 1);
    lsum0 += __shfl_xor_sync(0xffffffff, lsum0, 2);
    lsum1 += __shfl_xor_sync(0xffffffff, lsum1, 1);
    lsum1 += __shfl_xor_sync(0xffffffff, lsum1, 2);

    const int b = bh / NH, h = bh - (bh / NH) * NH;
    const float inv0 = 1.f / lsum0;
    const float inv1 = 1.f / lsum1;
    if (r0 < NTOK) {
        const size_t off = ((size_t)b * NTOK + r0) * DIM + h * HD;
#pragma unroll
        for (int nt = 0; nt < 8; nt++)
            *(uint32_t*)&g_aoF[off + nt * 8 + 2 * t] =
                pack_f16(oacc[nt][0] * inv0, oacc[nt][1] * inv0);
    }
    if (r1 < NTOK) {
        const size_t off = ((size_t)b * NTOK + r1) * DIM + h * HD;
#pragma unroll
        for (int nt = 0; nt < 8; nt++)
            *(uint32_t*)&g_aoF[off + nt * 8 + 2 * t] =
                pack_f16(oacc[nt][2] * inv1, oacc[nt][3] * inv1);
    }
}

// =========================================================================
extern "C" void kernel_launch(void* const* d_in, const int* in_sizes, int n_in,
                              void* d_out, int out_size)
{
    const float* x      = (const float*)d_in[0];
    const float* qkv_w  = (const float*)d_in[1];
    const float* qkv_b  = (const float*)d_in[2];
    const float* relh   = (const float*)d_in[3];
    const float* relw   = (const float*)d_in[4];
    const float* proj_w = (const float*)d_in[5];
    const float* proj_b = (const float*)d_in[6];
    float* out = (float*)d_out;

    cudaFuncSetAttribute(attn_mma,
                         cudaFuncAttributeMaxDynamicSharedMemorySize, ATT_SMEM);

    // 0) one-shot fp16 converts
    {
        const int n2x = MTOT * DIM / 2;
        split_kernel<0><<<(n2x + 255) / 256, 256>>>(x, n2x);
        const int n2q = 3 * DIM * DIM / 2;
        split_kernel<1><<<(n2q + 255) / 256, 256>>>(qkv_w, n2q);
        const int n2p = DIM * DIM / 2;
        split_kernel<2><<<(n2p + 255) / 256, 256>>>(proj_w, n2p);
    }

    // 1) QKV GEMM (1-term, double-buffered) -> g_q, g_k hi/lo, g_v hi/lo T
    gemm_mma<0><<<dim3(2304 / 128, MTOT / 128), 256>>>(qkv_b, nullptr);

    // 2) tensor-core flash attention per (b, head) -> g_aoF
    attn_mma<<<BATCH * NH, ATHR, ATT_SMEM>>>(relh, relw);

    // 3) proj GEMM (1-term, double-buffered) -> d_out
    gemm_mma<1><<<dim3(DIM / 128, MTOT / 128), 256>>>(proj_b, out);
}

// round 14
// speedup vs baseline: 2.0980x; 1.3320x over previous
#include <cuda_runtime.h>
#include <cuda_fp16.h>
#include <cstdint>

// ---------------- problem constants ----------------
#define BATCH   256
#define NH      12
#define HD      64
#define DIM     768          // NH*HD
#define WIN     14
#define NTOK    196          // WIN*WIN
#define NPAD    256          // padded token count for K/V tiles
#define MTOT    (BATCH*NTOK) // 50176
#define REL     27           // 2*WIN-1
#define RSTR    68           // padded rel-table row stride (floats)

// ---------------- scratch (device globals; no allocation allowed) -------
__device__ float g_q[BATCH*NH*NTOK*HD];                      // fp32, q*0.125
__device__ __half g_kH[BATCH*NH*NPAD*HD], g_kL[BATCH*NH*NPAD*HD]; // [b][h][n][d] hi/lo
__device__ __half g_vH[BATCH*NH*HD*NPAD], g_vL[BATCH*NH*HD*NPAD]; // [b][h][d][n] hi/lo
__device__ __half g_xF[MTOT*DIM];                            // x single fp16
__device__ __half g_wqF[3*DIM*DIM];                          // qkv_w single fp16
__device__ __half g_wpF[DIM*DIM];                            // proj_w single fp16
__device__ __half g_aoF[MTOT*DIM];                           // attn out single fp16

// =========================================================================
// helpers
// =========================================================================
__device__ __forceinline__ void mma_f16(float c[4],
                                        uint32_t a0, uint32_t a1, uint32_t a2, uint32_t a3,
                                        uint32_t b0, uint32_t b1)
{
    asm("mma.sync.aligned.m16n8k16.row.col.f32.f16.f16.f32 "
        "{%0,%1,%2,%3}, {%4,%5,%6,%7}, {%8,%9}, {%0,%1,%2,%3};"
        : "+f"(c[0]), "+f"(c[1]), "+f"(c[2]), "+f"(c[3])
        : "r"(a0), "r"(a1), "r"(a2), "r"(a3), "r"(b0), "r"(b1));
}

#define LDSM_X4(r0, r1, r2, r3, addr) \
    asm volatile("ldmatrix.sync.aligned.m8n8.x4.shared.b16 {%0,%1,%2,%3}, [%4];" \
        : "=r"(r0), "=r"(r1), "=r"(r2), "=r"(r3) : "r"(addr))

__device__ __forceinline__ uint32_t pack_f16(float x0, float x1)
{
    uint32_t h;
    asm("cvt.rn.f16x2.f32 %0, %1, %2;" : "=r"(h) : "f"(x1), "f"(x0));
    return h;
}

// (x0,x1) -> f16x2 hi + f16x2 residual lo
__device__ __forceinline__ void pack_hl16(float x0, float x1, uint32_t& hi, uint32_t& lo)
{
    uint32_t h;
    asm("cvt.rn.f16x2.f32 %0, %1, %2;" : "=r"(h) : "f"(x1), "f"(x0));
    __half2 hh = *reinterpret_cast<__half2*>(&h);
    float h0 = __low2float(hh);
    float h1 = __high2float(hh);
    uint32_t l;
    asm("cvt.rn.f16x2.f32 %0, %1, %2;" : "=r"(l) : "f"(x1 - h1), "f"(x0 - h0));
    hi = h; lo = l;
}

__device__ __forceinline__ void cp16(uint32_t dst, const void* src)
{
    asm volatile("cp.async.cg.shared.global [%0], [%1], 16;" :: "r"(dst), "l"(src));
}
#define CP_COMMIT() asm volatile("cp.async.commit_group;")
#define CP_WAIT(n)  asm volatile("cp.async.wait_group %0;" :: "n"(n))

// =========================================================================
// one-shot fp32 -> single fp16 convert kernels
// =========================================================================
template<int WHICH>
__global__ __launch_bounds__(256) void split_kernel(const float* __restrict__ src, int n2)
{
    const int i = blockIdx.x * 256 + threadIdx.x;
    if (i >= n2) return;
    float2 v = ((const float2*)src)[i];
    uint32_t p = pack_f16(v.x, v.y);
    if (WHICH == 0)      ((uint32_t*)g_xF)[i]  = p;
    else if (WHICH == 1) ((uint32_t*)g_wqF)[i] = p;
    else                 ((uint32_t*)g_wpF)[i] = p;
}

// =========================================================================
// fp16 1-term GEMM, double-buffered smem, ONE sync per iteration, LDSM
// fragment loads. CTA tile 128x128, BK=32, 256 threads = 8 warps (2Mx4N).
// =========================================================================
#define KSTR 40                       // fp16 smem row stride
#define TILE_BYTES (128*KSTR*2)       // 10240 B per tile

template<int MODE>
__global__ __launch_bounds__(256) void gemm_mma(const float* __restrict__ bias,
                                                float* __restrict__ out)
{
    __shared__ __half AsF[2][128 * KSTR];
    __shared__ __half BsF[2][128 * KSTR];

    const int tid = threadIdx.x;
    const int m0  = blockIdx.y * 128;
    const int n0  = blockIdx.x * 128;

    const int w    = tid >> 5;
    const int lane = tid & 31;
    const int g    = lane >> 2;
    const int t    = lane & 3;
    const int wm   = (w >> 2) * 64;
    const int wn   = (w & 3) * 32;

    const int lr = tid >> 2;          // 0..63
    const int lc = (tid & 3) * 8;     // fp16 col 0,8,16,24
    const int ro0 = lr * KSTR + lc;

    const __half* gA = (MODE ? g_aoF : g_xF) + (size_t)(m0 + lr) * 768 + lc;
    const __half* gB = (MODE ? g_wpF : g_wqF) + (size_t)(n0 + lr) * 768 + lc;
    const size_t rstep = (size_t)64 * 768;

    // LDSM per-lane base offsets (halves)
    const uint32_t asbase = (uint32_t)__cvta_generic_to_shared(AsF);
    const uint32_t bsbase = (uint32_t)__cvta_generic_to_shared(BsF);
    const int a_row = wm + (lane & 15);                 // + mt*16
    const int a_col = (lane >> 4) * 8;                  // + ks*16
    const int b_row = wn + (lane & 7) + (lane >> 4) * 8; // + ntp*8
    const int b_col = ((lane >> 3) & 1) * 8;            // + ks*16

    float acc[4][4][4];
#pragma unroll
    for (int i = 0; i < 4; i++)
#pragma unroll
        for (int j = 0; j < 4; j++)
#pragma unroll
            for (int r = 0; r < 4; r++) acc[i][j][r] = 0.f;

    uint4 pa[2], pb[2];
    pa[0] = *(const uint4*)(gA);          pa[1] = *(const uint4*)(gA + rstep);
    pb[0] = *(const uint4*)(gB);          pb[1] = *(const uint4*)(gB + rstep);
    *(uint4*)&AsF[0][ro0]             = pa[0];
    *(uint4*)&AsF[0][ro0 + 64 * KSTR] = pa[1];
    *(uint4*)&BsF[0][ro0]             = pb[0];
    *(uint4*)&BsF[0][ro0 + 64 * KSTR] = pb[1];
    __syncthreads();

    for (int i = 0; i < 24; i++) {
        const int cur = i & 1;
        const bool more = (i + 1 < 24);

        if (more) {
            const int k1 = (i + 1) * 32;
            pa[0] = *(const uint4*)(gA + k1);          pa[1] = *(const uint4*)(gA + k1 + rstep);
            pb[0] = *(const uint4*)(gB + k1);          pb[1] = *(const uint4*)(gB + k1 + rstep);
        }

        const uint32_t sA = asbase + cur * TILE_BYTES;
        const uint32_t sB = bsbase + cur * TILE_BYTES;
#pragma unroll
        for (int ks = 0; ks < 2; ks++) {
            uint32_t a[4][4], b[4][2];
#pragma unroll
            for (int mt = 0; mt < 4; mt++) {
                const uint32_t ad = sA + ((a_row + mt * 16) * KSTR + ks * 16 + a_col) * 2;
                LDSM_X4(a[mt][0], a[mt][1], a[mt][2], a[mt][3], ad);
            }
#pragma unroll
            for (int ntp = 0; ntp < 4; ntp += 2) {
                const uint32_t bd = sB + ((b_row + ntp * 8) * KSTR + ks * 16 + b_col) * 2;
                LDSM_X4(b[ntp][0], b[ntp][1], b[ntp + 1][0], b[ntp + 1][1], bd);
            }
#pragma unroll
            for (int mt = 0; mt < 4; mt++)
#pragma unroll
                for (int nt = 0; nt < 4; nt++)
                    mma_f16(acc[mt][nt], a[mt][0], a[mt][1], a[mt][2], a[mt][3],
                            b[nt][0], b[nt][1]);
        }

        if (more) {
            const int nxt = cur ^ 1;
            *(uint4*)&AsF[nxt][ro0]             = pa[0];
            *(uint4*)&AsF[nxt][ro0 + 64 * KSTR] = pa[1];
            *(uint4*)&BsF[nxt][ro0]             = pb[0];
            *(uint4*)&BsF[nxt][ro0 + 64 * KSTR] = pb[1];
        }
        __syncthreads();
    }

    // ----- epilogue -----
#pragma unroll
    for (int mt = 0; mt < 4; mt++) {
#pragma unroll
        for (int half = 0; half < 2; half++) {
            const int m = m0 + wm + mt * 16 + g + half * 8;
            if (MODE == 0) {
                const int b = m / NTOK;
                const int n = m - b * NTOK;
#pragma unroll
                for (int nt = 0; nt < 4; nt++) {
                    const int col0 = n0 + wn + nt * 8 + 2 * t;
                    float v0 = acc[mt][nt][half * 2 + 0] + bias[col0];
                    float v1 = acc[mt][nt][half * 2 + 1] + bias[col0 + 1];
                    const int which = col0 / DIM;
                    const int rem   = col0 - which * DIM;
                    const int h     = rem >> 6;
                    const int dd    = rem & 63;
                    const int bhI   = b * NH + h;
                    if (which == 0) {
                        float2 q2 = make_float2(v0 * 0.125f, v1 * 0.125f);
                        *(float2*)&g_q[((size_t)bhI * NTOK + n) * HD + dd] = q2;
                    } else if (which == 1) {
                        uint32_t hp, lp;
                        pack_hl16(v0, v1, hp, lp);
                        const size_t idx = ((size_t)bhI * NPAD + n) * HD + dd;
                        *(uint32_t*)&g_kH[idx] = hp;
                        *(uint32_t*)&g_kL[idx] = lp;
                    } else { // V transposed [d][n], hi/lo
                        const size_t i0 = ((size_t)bhI * HD + dd) * NPAD + n;
                        __half h0 = __float2half_rn(v0);
                        __half h1 = __float2half_rn(v1);
                        g_vH[i0]        = h0;
                        g_vH[i0 + NPAD] = h1;
                        g_vL[i0]        = __float2half_rn(v0 - __half2float(h0));
                        g_vL[i0 + NPAD] = __float2half_rn(v1 - __half2float(h1));
                    }
                }
            } else {
#pragma unroll
                for (int nt = 0; nt < 4; nt++) {
                    const int col = n0 + wn + nt * 8 + 2 * t;
                    float2 v;
                    v.x = acc[mt][nt][half * 2 + 0] + bias[col];
                    v.y = acc[mt][nt][half * 2 + 1] + bias[col + 1];
                    *(float2*)&out[(size_t)m * DIM + col] = v;
                }
            }
        }
    }
}

// =========================================================================
// Tensor-core flash attention. REL tables padded to stride 68 floats
// (conflict-free strided float4 loads). Otherwise round-13 structure.
// =========================================================================
#define KS_STR  72
#define KV_TILE (64*KS_STR*2)
#define KV_STAGE (4*KV_TILE)
#define SRH_OFF 0
#define SRW_OFF (SRH_OFF + REL*RSTR*4)            // 7344
#define SBH_OFF (SRW_OFF + REL*RSTR*4)            // 14688
#define SBW_OFF (SBH_OFF + 208*14*4)              // 26336
#define SKV_OFF (SBW_OFF + 208*14*4)              // 37984
#define ATT_SMEM (SKV_OFF + 2*KV_STAGE)           // 111712 B

#define ATHR 416

__global__ __launch_bounds__(ATHR, 1) void attn_mma(const float* __restrict__ relh,
                                                    const float* __restrict__ relw)
{
    extern __shared__ char smc[];
    float* RH = (float*)(smc + SRH_OFF);
    float* RW = (float*)(smc + SRW_OFF);
    float* BH = (float*)(smc + SBH_OFF);
    float* BW = (float*)(smc + SBW_OFF);

    const int bh  = blockIdx.x;
    const int tid = threadIdx.x;
    const int w    = tid >> 5;
    const int lane = tid & 31;
    const int g    = lane >> 2;
    const int t    = lane & 3;

    const float* qg = g_q + (size_t)bh * NTOK * HD;
    const uint32_t kvbase = (uint32_t)__cvta_generic_to_shared(smc + SKV_OFF);

#define PREFETCH_CHUNK(j0, s)                                              \
    {                                                                      \
        for (int idx = tid; idx < 2048; idx += ATHR) {                     \
            const int tile = idx >> 9;                                     \
            const int r    = (idx >> 3) & 63;                              \
            const int c8   = idx & 7;                                      \
            const __half* src;                                             \
            if (tile == 0)      src = g_kH + ((size_t)bh * NPAD + (j0) + r) * HD + c8 * 8; \
            else if (tile == 1) src = g_kL + ((size_t)bh * NPAD + (j0) + r) * HD + c8 * 8; \
            else if (tile == 2) src = g_vH + ((size_t)bh * HD + r) * NPAD + (j0) + c8 * 8; \
            else                src = g_vL + ((size_t)bh * HD + r) * NPAD + (j0) + c8 * 8; \
            cp16(kvbase + (s) * KV_STAGE + tile * KV_TILE + r * (KS_STR*2) + c8 * 16, src); \
        }                                                                  \
        CP_COMMIT();                                                       \
    }

    PREFETCH_CHUNK(0, 0);

    // stage rel tables with padded stride (16 float4 per row of 64 floats)
    for (int idx = tid; idx < REL * 16; idx += ATHR) {
        const int r = idx >> 4, i4 = idx & 15;
        ((float4*)(RH + r * RSTR))[i4] = ((const float4*)relh)[idx];
        ((float4*)(RW + r * RSTR))[i4] = ((const float4*)relw)[idx];
    }
    __syncthreads();

    if (tid < NTOK) {
        float4 q4[16];
        const float4* qr = (const float4*)(qg + tid * HD);
#pragma unroll
        for (int i = 0; i < 16; i++) q4[i] = qr[i];
        const int qh = tid / WIN, qw = tid - qh * WIN;
#pragma unroll 1
        for (int kk = 0; kk < WIN; kk++) {
            const float4* rh4 = (const float4*)(RH + (qh - kk + WIN - 1) * RSTR);
            const float4* rw4 = (const float4*)(RW + (qw - kk + WIN - 1) * RSTR);
            float sh = 0.f, sw = 0.f;
#pragma unroll
            for (int i = 0; i < 16; i++) {
                float4 a = q4[i], r = rh4[i], wv = rw4[i];
                sh += a.x * r.x + a.y * r.y + a.z * r.z + a.w * r.w;
                sw += a.x * wv.x + a.y * wv.y + a.z * wv.z + a.w * wv.w;
            }
            BH[tid * WIN + kk] = sh;
            BW[tid * WIN + kk] = sw;
        }
    } else if (tid < 208) {
#pragma unroll
        for (int kk = 0; kk < WIN; kk++) {
            BH[tid * WIN + kk] = 0.f;
            BW[tid * WIN + kk] = 0.f;
        }
    }

    // Q fragments: single fp16
    const int r0 = w * 16 + g;
    const int r1 = r0 + 8;
    const int rq0 = (r0 < NTOK) ? r0 : NTOK - 1;
    const int rq1 = (r1 < NTOK) ? r1 : NTOK - 1;
    uint32_t qf[4][4];
#pragma unroll
    for (int kt = 0; kt < 4; kt++) {
        const int kc = kt * 16 + 2 * t;
        float2 v0 = *(const float2*)(qg + rq0 * HD + kc);
        float2 v1 = *(const float2*)(qg + rq1 * HD + kc);
        float2 v2 = *(const float2*)(qg + rq0 * HD + kc + 8);
        float2 v3 = *(const float2*)(qg + rq1 * HD + kc + 8);
        qf[kt][0] = pack_f16(v0.x, v0.y);
        qf[kt][1] = pack_f16(v1.x, v1.y);
        qf[kt][2] = pack_f16(v2.x, v2.y);
        qf[kt][3] = pack_f16(v3.x, v3.y);
    }

    float oacc[8][4];
#pragma unroll
    for (int j = 0; j < 8; j++)
#pragma unroll
        for (int r = 0; r < 4; r++) oacc[j][r] = 0.f;
    float lsum0 = 0.f, lsum1 = 0.f;

#pragma unroll 1
    for (int chunk = 0; chunk < 4; chunk++) {
        const int j0 = chunk * 64;
        const int s  = chunk & 1;
        CP_WAIT(0);
        __syncthreads();
        if (chunk < 3) PREFETCH_CHUNK(j0 + 64, s ^ 1);

        const __half* KH = (const __half*)(smc + SKV_OFF + s * KV_STAGE);
        const __half* KL = KH + 64 * KS_STR;
        const __half* VH = KH + 2 * 64 * KS_STR;
        const __half* VL = KH + 3 * 64 * KS_STR;

        float sacc[8][4];
#pragma unroll
        for (int j = 0; j < 8; j++)
#pragma unroll
            for (int r = 0; r < 4; r++) sacc[j][r] = 0.f;

#pragma unroll
        for (int kt = 0; kt < 4; kt++) {
            const int kc = kt * 16 + 2 * t;
#pragma unroll
            for (int nt = 0; nt < 8; nt++) {
                const int krow = (nt * 8 + g) * KS_STR + kc;
                uint32_t kh0 = *(const uint32_t*)&KH[krow];
                uint32_t kh1 = *(const uint32_t*)&KH[krow + 8];
                uint32_t kl0 = *(const uint32_t*)&KL[krow];
                uint32_t kl1 = *(const uint32_t*)&KL[krow + 8];
                mma_f16(sacc[nt], qf[kt][0], qf[kt][1], qf[kt][2], qf[kt][3], kl0, kl1);
                mma_f16(sacc[nt], qf[kt][0], qf[kt][1], qf[kt][2], qf[kt][3], kh0, kh1);
            }
        }

#pragma unroll
        for (int nt = 0; nt < 8; nt++) {
#pragma unroll
            for (int e = 0; e < 2; e++) {
                const int c = j0 + nt * 8 + 2 * t + e;
                float p0 = 0.f, p1 = 0.f;
                if (c < NTOK) {
                    const int kh = c / WIN;
                    const int kw = c - kh * WIN;
                    p0 = __expf(sacc[nt][e]     + BH[r0 * WIN + kh] + BW[r0 * WIN + kw]);
                    p1 = __expf(sacc[nt][2 + e] + BH[r1 * WIN + kh] + BW[r1 * WIN + kw]);
                }
                sacc[nt][e]     = p0;
                sacc[nt][2 + e] = p1;
                lsum0 += p0;
                lsum1 += p1;
            }
        }

#pragma unroll
        for (int kt = 0; kt < 4; kt++) {
            uint32_t ph[4];
            ph[0] = pack_f16(sacc[2*kt][0],   sacc[2*kt][1]);
            ph[1] = pack_f16(sacc[2*kt][2],   sacc[2*kt][3]);
            ph[2] = pack_f16(sacc[2*kt+1][0], sacc[2*kt+1][1]);
            ph[3] = pack_f16(sacc[2*kt+1][2], sacc[2*kt+1][3]);
            const int kc = kt * 16 + 2 * t;
#pragma unroll
            for (int nt = 0; nt < 8; nt++) {
                const int vrow = (nt * 8 + g) * KS_STR + kc;
                uint32_t vh0 = *(const uint32_t*)&VH[vrow];
                uint32_t vh1 = *(const uint32_t*)&VH[vrow + 8];
                uint32_t vl0 = *(const uint32_t*)&VL[vrow];
                uint32_t vl1 = *(const uint32_t*)&VL[vrow + 8];
                mma_f16(oacc[nt], ph[0], ph[1], ph[2], ph[3], vl0, vl1);
                mma_f16(oacc[nt], ph[0], ph[1], ph[2], ph[3], vh0, vh1);
            }
        }
    }

    lsum0 += __shfl_xor_sync(0xffffffff, lsum0, 1);
    lsum0 += __shfl_xor_sync(0xffffffff, lsum0, 2);
    lsum1 += __shfl_xor_sync(0xffffffff, lsum1, 1);
    lsum1 += __shfl_xor_sync(0xffffffff, lsum1, 2);

    const int b = bh / NH, h = bh - (bh / NH) * NH;
    const float inv0 = 1.f / lsum0;
    const float inv1 = 1.f / lsum1;
    if (r0 < NTOK) {
        const size_t off = ((size_t)b * NTOK + r0) * DIM + h * HD;
#pragma unroll
        for (int nt = 0; nt < 8; nt++)
            *(uint32_t*)&g_aoF[off + nt * 8 + 2 * t] =
                pack_f16(oacc[nt][0] * inv0, oacc[nt][1] * inv0);
    }
    if (r1 < NTOK) {
        const size_t off = ((size_t)b * NTOK + r1) * DIM + h * HD;
#pragma unroll
        for (int nt = 0; nt < 8; nt++)
            *(uint32_t*)&g_aoF[off + nt * 8 + 2 * t] =
                pack_f16(oacc[nt][2] * inv1, oacc[nt][3] * inv1);
    }
}

// =========================================================================
extern "C" void kernel_launch(void* const* d_in, const int* in_sizes, int n_in,
                              void* d_out, int out_size)
{
    const float* x      = (const float*)d_in[0];
    const float* qkv_w  = (const float*)d_in[1];
    const float* qkv_b  = (const float*)d_in[2];
    const float* relh   = (const float*)d_in[3];
    const float* relw   = (const float*)d_in[4];
    const float* proj_w = (const float*)d_in[5];
    const float* proj_b = (const float*)d_in[6];
    float* out = (float*)d_out;

    cudaFuncSetAttribute(attn_mma,
                         cudaFuncAttributeMaxDynamicSharedMemorySize, ATT_SMEM);

    // 0) one-shot fp16 converts
    {
        const int n2x = MTOT * DIM / 2;
        split_kernel<0><<<(n2x + 255) / 256, 256>>>(x, n2x);
        const int n2q = 3 * DIM * DIM / 2;
        split_kernel<1><<<(n2q + 255) / 256, 256>>>(qkv_w, n2q);
        const int n2p = DIM * DIM / 2;
        split_kernel<2><<<(n2p + 255) / 256, 256>>>(proj_w, n2p);
    }

    // 1) QKV GEMM (1-term, LDSM) -> g_q, g_k hi/lo, g_v hi/lo transposed
    gemm_mma<0><<<dim3(2304 / 128, MTOT / 128), 256>>>(qkv_b, nullptr);

    // 2) tensor-core flash attention per (b, head) -> g_aoF
    attn_mma<<<BATCH * NH, ATHR, ATT_SMEM>>>(relh, relw);

    // 3) proj GEMM (1-term, LDSM) -> d_out
    gemm_mma<1><<<dim3(DIM / 128, MTOT / 128), 256>>>(proj_b, out);
}

// round 15
// speedup vs baseline: 2.4003x; 1.1441x over previous
#include <cuda_runtime.h>
#include <cuda_fp16.h>
#include <cstdint>

// ---------------- problem constants ----------------
#define BATCH   256
#define NH      12
#define HD      64
#define DIM     768          // NH*HD
#define WIN     14
#define NTOK    196          // WIN*WIN
#define NPAD    256          // padded token count for K/V tiles
#define MTOT    (BATCH*NTOK) // 50176
#define REL     27           // 2*WIN-1
#define RSTR    68           // padded rel-table row stride (floats)

// ---------------- scratch (device globals; no allocation allowed) -------
__device__ float g_q[BATCH*NH*NTOK*HD];                      // fp32, q*0.125
__device__ __half g_kF[BATCH*NH*NPAD*HD];                    // [b][h][n][d] single fp16
__device__ __half g_vF[BATCH*NH*HD*NPAD];                    // [b][h][d][n] single fp16
__device__ __half g_xF[MTOT*DIM];                            // x single fp16
__device__ __half g_wqF[3*DIM*DIM];                          // qkv_w single fp16
__device__ __half g_wpF[DIM*DIM];                            // proj_w single fp16
__device__ __half g_aoF[MTOT*DIM];                           // attn out single fp16

// =========================================================================
// helpers
// =========================================================================
__device__ __forceinline__ void mma_f16(float c[4],
                                        uint32_t a0, uint32_t a1, uint32_t a2, uint32_t a3,
                                        uint32_t b0, uint32_t b1)
{
    asm("mma.sync.aligned.m16n8k16.row.col.f32.f16.f16.f32 "
        "{%0,%1,%2,%3}, {%4,%5,%6,%7}, {%8,%9}, {%0,%1,%2,%3};"
        : "+f"(c[0]), "+f"(c[1]), "+f"(c[2]), "+f"(c[3])
        : "r"(a0), "r"(a1), "r"(a2), "r"(a3), "r"(b0), "r"(b1));
}

#define LDSM_X4(r0, r1, r2, r3, addr) \
    asm volatile("ldmatrix.sync.aligned.m8n8.x4.shared.b16 {%0,%1,%2,%3}, [%4];" \
        : "=r"(r0), "=r"(r1), "=r"(r2), "=r"(r3) : "r"(addr))

__device__ __forceinline__ uint32_t pack_f16(float x0, float x1)
{
    uint32_t h;
    asm("cvt.rn.f16x2.f32 %0, %1, %2;" : "=r"(h) : "f"(x1), "f"(x0));
    return h;
}

__device__ __forceinline__ void cp16(uint32_t dst, const void* src)
{
    asm volatile("cp.async.cg.shared.global [%0], [%1], 16;" :: "r"(dst), "l"(src));
}
#define CP_COMMIT() asm volatile("cp.async.commit_group;")
#define CP_WAIT(n)  asm volatile("cp.async.wait_group %0;" :: "n"(n))

// =========================================================================
// one-shot fp32 -> single fp16 convert kernels
// =========================================================================
template<int WHICH>
__global__ __launch_bounds__(256) void split_kernel(const float* __restrict__ src, int n2)
{
    const int i = blockIdx.x * 256 + threadIdx.x;
    if (i >= n2) return;
    float2 v = ((const float2*)src)[i];
    uint32_t p = pack_f16(v.x, v.y);
    if (WHICH == 0)      ((uint32_t*)g_xF)[i]  = p;
    else if (WHICH == 1) ((uint32_t*)g_wqF)[i] = p;
    else                 ((uint32_t*)g_wpF)[i] = p;
}

// =========================================================================
// fp16 1-term GEMM, double-buffered smem, ONE sync per iteration, LDSM
// fragment loads (hoisted addresses). 128x128 CTA tile, BK=32, 256 thr.
// =========================================================================
#define KSTR 40                       // fp16 smem row stride
#define TILE_BYTES (128*KSTR*2)       // 10240 B per tile

template<int MODE>
__global__ __launch_bounds__(256) void gemm_mma(const float* __restrict__ bias,
                                                float* __restrict__ out)
{
    __shared__ __half AsF[2][128 * KSTR];
    __shared__ __half BsF[2][128 * KSTR];

    const int tid = threadIdx.x;
    const int m0  = blockIdx.y * 128;
    const int n0  = blockIdx.x * 128;

    const int w    = tid >> 5;
    const int lane = tid & 31;
    const int g    = lane >> 2;
    const int t    = lane & 3;
    const int wm   = (w >> 2) * 64;
    const int wn   = (w & 3) * 32;

    const int lr = tid >> 2;          // 0..63
    const int lc = (tid & 3) * 8;     // fp16 col 0,8,16,24
    const int ro0 = lr * KSTR + lc;

    const __half* gA = (MODE ? g_aoF : g_xF) + (size_t)(m0 + lr) * 768 + lc;
    const __half* gB = (MODE ? g_wpF : g_wqF) + (size_t)(n0 + lr) * 768 + lc;
    const size_t rstep = (size_t)64 * 768;

    // hoisted LDSM addresses (stage 0); add TILE_BYTES for stage 1, 32B per ks
    uint32_t a_addr[4], b_addr[2];
    {
        const uint32_t asb = (uint32_t)__cvta_generic_to_shared(AsF);
        const uint32_t bsb = (uint32_t)__cvta_generic_to_shared(BsF);
        const int ar = wm + (lane & 15);
        const int ac = (lane >> 4) * 8;
        const int br = wn + (lane & 7) + (lane >> 4) * 8;
        const int bc = ((lane >> 3) & 1) * 8;
#pragma unroll
        for (int mt = 0; mt < 4; mt++)
            a_addr[mt] = asb + ((ar + mt * 16) * KSTR + ac) * 2;
#pragma unroll
        for (int ntp = 0; ntp < 2; ntp++)
            b_addr[ntp] = bsb + ((br + ntp * 16) * KSTR + bc) * 2;
    }

    float acc[4][4][4];
#pragma unroll
    for (int i = 0; i < 4; i++)
#pragma unroll
        for (int j = 0; j < 4; j++)
#pragma unroll
            for (int r = 0; r < 4; r++) acc[i][j][r] = 0.f;

    uint4 pa[2], pb[2];
    pa[0] = *(const uint4*)(gA);          pa[1] = *(const uint4*)(gA + rstep);
    pb[0] = *(const uint4*)(gB);          pb[1] = *(const uint4*)(gB + rstep);
    *(uint4*)&AsF[0][ro0]             = pa[0];
    *(uint4*)&AsF[0][ro0 + 64 * KSTR] = pa[1];
    *(uint4*)&BsF[0][ro0]             = pb[0];
    *(uint4*)&BsF[0][ro0 + 64 * KSTR] = pb[1];
    __syncthreads();

    for (int i = 0; i < 24; i++) {
        const int cur = i & 1;
        const bool more = (i + 1 < 24);

        if (more) {
            const int k1 = (i + 1) * 32;
            pa[0] = *(const uint4*)(gA + k1);          pa[1] = *(const uint4*)(gA + k1 + rstep);
            pb[0] = *(const uint4*)(gB + k1);          pb[1] = *(const uint4*)(gB + k1 + rstep);
        }

        const uint32_t so = cur * TILE_BYTES;
#pragma unroll
        for (int ks = 0; ks < 2; ks++) {
            const uint32_t ko = so + ks * 32;
            uint32_t a[4][4], b[4][2];
#pragma unroll
            for (int mt = 0; mt < 4; mt++)
                LDSM_X4(a[mt][0], a[mt][1], a[mt][2], a[mt][3], a_addr[mt] + ko);
            LDSM_X4(b[0][0], b[0][1], b[1][0], b[1][1], b_addr[0] + ko);
            LDSM_X4(b[2][0], b[2][1], b[3][0], b[3][1], b_addr[1] + ko);
#pragma unroll
            for (int mt = 0; mt < 4; mt++)
#pragma unroll
                for (int nt = 0; nt < 4; nt++)
                    mma_f16(acc[mt][nt], a[mt][0], a[mt][1], a[mt][2], a[mt][3],
                            b[nt][0], b[nt][1]);
        }

        if (more) {
            const int nxt = cur ^ 1;
            *(uint4*)&AsF[nxt][ro0]             = pa[0];
            *(uint4*)&AsF[nxt][ro0 + 64 * KSTR] = pa[1];
            *(uint4*)&BsF[nxt][ro0]             = pb[0];
            *(uint4*)&BsF[nxt][ro0 + 64 * KSTR] = pb[1];
        }
        __syncthreads();
    }

    // ----- epilogue -----
#pragma unroll
    for (int mt = 0; mt < 4; mt++) {
#pragma unroll
        for (int half = 0; half < 2; half++) {
            const int m = m0 + wm + mt * 16 + g + half * 8;
            if (MODE == 0) {
                const int b = m / NTOK;
                const int n = m - b * NTOK;
#pragma unroll
                for (int nt = 0; nt < 4; nt++) {
                    const int col0 = n0 + wn + nt * 8 + 2 * t;
                    float v0 = acc[mt][nt][half * 2 + 0] + bias[col0];
                    float v1 = acc[mt][nt][half * 2 + 1] + bias[col0 + 1];
                    const int which = col0 / DIM;
                    const int rem   = col0 - which * DIM;
                    const int h     = rem >> 6;
                    const int dd    = rem & 63;
                    const int bhI   = b * NH + h;
                    if (which == 0) {
                        float2 q2 = make_float2(v0 * 0.125f, v1 * 0.125f);
                        *(float2*)&g_q[((size_t)bhI * NTOK + n) * HD + dd] = q2;
                    } else if (which == 1) {
                        const size_t idx = ((size_t)bhI * NPAD + n) * HD + dd;
                        *(uint32_t*)&g_kF[idx] = pack_f16(v0, v1);
                    } else { // V transposed [d][n], single fp16
                        const size_t i0 = ((size_t)bhI * HD + dd) * NPAD + n;
                        g_vF[i0]        = __float2half_rn(v0);
                        g_vF[i0 + NPAD] = __float2half_rn(v1);
                    }
                }
            } else {
#pragma unroll
                for (int nt = 0; nt < 4; nt++) {
                    const int col = n0 + wn + nt * 8 + 2 * t;
                    float2 v;
                    v.x = acc[mt][nt][half * 2 + 0] + bias[col];
                    v.y = acc[mt][nt][half * 2 + 1] + bias[col + 1];
                    *(float2*)&out[(size_t)m * DIM + col] = v;
                }
            }
        }
    }
}

// =========================================================================
// Tensor-core flash attention: ALL single fp16 operands (Q, K, P, V).
// One CTA per (b,h), 416 threads = 13 warps, cp.async double buffer.
// =========================================================================
#define KS_STR  72
#define KV_TILE (64*KS_STR*2)                     // 9216 B
#define KV_STAGE (2*KV_TILE)                      // 18432 B (K + V)
#define SRH_OFF 0
#define SRW_OFF (SRH_OFF + REL*RSTR*4)            // 7344
#define SBH_OFF (SRW_OFF + REL*RSTR*4)            // 14688
#define SBW_OFF (SBH_OFF + 208*14*4)              // 26336
#define SKV_OFF (SBW_OFF + 208*14*4)              // 37984
#define ATT_SMEM (SKV_OFF + 2*KV_STAGE)           // 74848 B

#define ATHR 416

__global__ __launch_bounds__(ATHR, 1) void attn_mma(const float* __restrict__ relh,
                                                    const float* __restrict__ relw)
{
    extern __shared__ char smc[];
    float* RH = (float*)(smc + SRH_OFF);
    float* RW = (float*)(smc + SRW_OFF);
    float* BH = (float*)(smc + SBH_OFF);
    float* BW = (float*)(smc + SBW_OFF);

    const int bh  = blockIdx.x;
    const int tid = threadIdx.x;
    const int w    = tid >> 5;
    const int lane = tid & 31;
    const int g    = lane >> 2;
    const int t    = lane & 3;

    const float* qg = g_q + (size_t)bh * NTOK * HD;
    const uint32_t kvbase = (uint32_t)__cvta_generic_to_shared(smc + SKV_OFF);

#define PREFETCH_CHUNK(j0, s)                                              \
    {                                                                      \
        for (int idx = tid; idx < 1024; idx += ATHR) {                     \
            const int tile = idx >> 9;                                     \
            const int r    = (idx >> 3) & 63;                              \
            const int c8   = idx & 7;                                      \
            const __half* src;                                             \
            if (tile == 0) src = g_kF + ((size_t)bh * NPAD + (j0) + r) * HD + c8 * 8; \
            else           src = g_vF + ((size_t)bh * HD + r) * NPAD + (j0) + c8 * 8; \
            cp16(kvbase + (s) * KV_STAGE + tile * KV_TILE + r * (KS_STR*2) + c8 * 16, src); \
        }                                                                  \
        CP_COMMIT();                                                       \
    }

    PREFETCH_CHUNK(0, 0);

    // stage rel tables with padded stride (16 float4 per row of 64 floats)
    for (int idx = tid; idx < REL * 16; idx += ATHR) {
        const int r = idx >> 4, i4 = idx & 15;
        ((float4*)(RH + r * RSTR))[i4] = ((const float4*)relh)[idx];
        ((float4*)(RW + r * RSTR))[i4] = ((const float4*)relw)[idx];
    }
    __syncthreads();

    if (tid < NTOK) {
        float4 q4[16];
        const float4* qr = (const float4*)(qg + tid * HD);
#pragma unroll
        for (int i = 0; i < 16; i++) q4[i] = qr[i];
        const int qh = tid / WIN, qw = tid - qh * WIN;
#pragma unroll 1
        for (int kk = 0; kk < WIN; kk++) {
            const float4* rh4 = (const float4*)(RH + (qh - kk + WIN - 1) * RSTR);
            const float4* rw4 = (const float4*)(RW + (qw - kk + WIN - 1) * RSTR);
            float sh = 0.f, sw = 0.f;
#pragma unroll
            for (int i = 0; i < 16; i++) {
                float4 a = q4[i], r = rh4[i], wv = rw4[i];
                sh += a.x * r.x + a.y * r.y + a.z * r.z + a.w * r.w;
                sw += a.x * wv.x + a.y * wv.y + a.z * wv.z + a.w * wv.w;
            }
            BH[tid * WIN + kk] = sh;
            BW[tid * WIN + kk] = sw;
        }
    } else if (tid < 208) {
#pragma unroll
        for (int kk = 0; kk < WIN; kk++) {
            BH[tid * WIN + kk] = 0.f;
            BW[tid * WIN + kk] = 0.f;
        }
    }

    // Q fragments: single fp16
    const int r0 = w * 16 + g;
    const int r1 = r0 + 8;
    const int rq0 = (r0 < NTOK) ? r0 : NTOK - 1;
    const int rq1 = (r1 < NTOK) ? r1 : NTOK - 1;
    uint32_t qf[4][4];
#pragma unroll
    for (int kt = 0; kt < 4; kt++) {
        const int kc = kt * 16 + 2 * t;
        float2 v0 = *(const float2*)(qg + rq0 * HD + kc);
        float2 v1 = *(const float2*)(qg + rq1 * HD + kc);
        float2 v2 = *(const float2*)(qg + rq0 * HD + kc + 8);
        float2 v3 = *(const float2*)(qg + rq1 * HD + kc + 8);
        qf[kt][0] = pack_f16(v0.x, v0.y);
        qf[kt][1] = pack_f16(v1.x, v1.y);
        qf[kt][2] = pack_f16(v2.x, v2.y);
        qf[kt][3] = pack_f16(v3.x, v3.y);
    }

    float oacc[8][4];
#pragma unroll
    for (int j = 0; j < 8; j++)
#pragma unroll
        for (int r = 0; r < 4; r++) oacc[j][r] = 0.f;
    float lsum0 = 0.f, lsum1 = 0.f;

#pragma unroll 1
    for (int chunk = 0; chunk < 4; chunk++) {
        const int j0 = chunk * 64;
        const int s  = chunk & 1;
        CP_WAIT(0);
        __syncthreads();
        if (chunk < 3) PREFETCH_CHUNK(j0 + 64, s ^ 1);

        const __half* KF = (const __half*)(smc + SKV_OFF + s * KV_STAGE);
        const __half* VF = KF + 64 * KS_STR;

        float sacc[8][4];
#pragma unroll
        for (int j = 0; j < 8; j++)
#pragma unroll
            for (int r = 0; r < 4; r++) sacc[j][r] = 0.f;

#pragma unroll
        for (int kt = 0; kt < 4; kt++) {
            const int kc = kt * 16 + 2 * t;
#pragma unroll
            for (int nt = 0; nt < 8; nt++) {
                const int krow = (nt * 8 + g) * KS_STR + kc;
                uint32_t k0 = *(const uint32_t*)&KF[krow];
                uint32_t k1 = *(const uint32_t*)&KF[krow + 8];
                mma_f16(sacc[nt], qf[kt][0], qf[kt][1], qf[kt][2], qf[kt][3], k0, k1);
            }
        }

#pragma unroll
        for (int nt = 0; nt < 8; nt++) {
#pragma unroll
            for (int e = 0; e < 2; e++) {
                const int c = j0 + nt * 8 + 2 * t + e;
                float p0 = 0.f, p1 = 0.f;
                if (c < NTOK) {
                    const int kh = c / WIN;
                    const int kw = c - kh * WIN;
                    p0 = __expf(sacc[nt][e]     + BH[r0 * WIN + kh] + BW[r0 * WIN + kw]);
                    p1 = __expf(sacc[nt][2 + e] + BH[r1 * WIN + kh] + BW[r1 * WIN + kw]);
                }
                sacc[nt][e]     = p0;
                sacc[nt][2 + e] = p1;
                lsum0 += p0;
                lsum1 += p1;
            }
        }

#pragma unroll
        for (int kt = 0; kt < 4; kt++) {
            uint32_t ph[4];
            ph[0] = pack_f16(sacc[2*kt][0],   sacc[2*kt][1]);
            ph[1] = pack_f16(sacc[2*kt][2],   sacc[2*kt][3]);
            ph[2] = pack_f16(sacc[2*kt+1][0], sacc[2*kt+1][1]);
            ph[3] = pack_f16(sacc[2*kt+1][2], sacc[2*kt+1][3]);
            const int kc = kt * 16 + 2 * t;
#pragma unroll
            for (int nt = 0; nt < 8; nt++) {
                const int vrow = (nt * 8 + g) * KS_STR + kc;
                uint32_t v0 = *(const uint32_t*)&VF[vrow];
                uint32_t v1 = *(const uint32_t*)&VF[vrow + 8];
                mma_f16(oacc[nt], ph[0], ph[1], ph[2], ph[3], v0, v1);
            }
        }
    }

    lsum0 += __shfl_xor_sync(0xffffffff, lsum0, 1);
    lsum0 += __shfl_xor_sync(0xffffffff, lsum0, 2);
    lsum1 += __shfl_xor_sync(0xffffffff, lsum1, 1);
    lsum1 += __shfl_xor_sync(0xffffffff, lsum1, 2);

    const int b = bh / NH, h = bh - (bh / NH) * NH;
    const float inv0 = 1.f / lsum0;
    const float inv1 = 1.f / lsum1;
    if (r0 < NTOK) {
        const size_t off = ((size_t)b * NTOK + r0) * DIM + h * HD;
#pragma unroll
        for (int nt = 0; nt < 8; nt++)
            *(uint32_t*)&g_aoF[off + nt * 8 + 2 * t] =
                pack_f16(oacc[nt][0] * inv0, oacc[nt][1] * inv0);
    }
    if (r1 < NTOK) {
        const size_t off = ((size_t)b * NTOK + r1) * DIM + h * HD;
#pragma unroll
        for (int nt = 0; nt < 8; nt++)
            *(uint32_t*)&g_aoF[off + nt * 8 + 2 * t] =
                pack_f16(oacc[nt][2] * inv1, oacc[nt][3] * inv1);
    }
}

// =========================================================================
extern "C" void kernel_launch(void* const* d_in, const int* in_sizes, int n_in,
                              void* d_out, int out_size)
{
    const float* x      = (const float*)d_in[0];
    const float* qkv_w  = (const float*)d_in[1];
    const float* qkv_b  = (const float*)d_in[2];
    const float* relh   = (const float*)d_in[3];
    const float* relw   = (const float*)d_in[4];
    const float* proj_w = (const float*)d_in[5];
    const float* proj_b = (const float*)d_in[6];
    float* out = (float*)d_out;

    cudaFuncSetAttribute(attn_mma,
                         cudaFuncAttributeMaxDynamicSharedMemorySize, ATT_SMEM);

    // 0) one-shot fp16 converts
    {
        const int n2x = MTOT * DIM / 2;
        split_kernel<0><<<(n2x + 255) / 256, 256>>>(x, n2x);
        const int n2q = 3 * DIM * DIM / 2;
        split_kernel<1><<<(n2q + 255) / 256, 256>>>(qkv_w, n2q);
        const int n2p = DIM * DIM / 2;
        split_kernel<2><<<(n2p + 255) / 256, 256>>>(proj_w, n2p);
    }

    // 1) QKV GEMM (1-term, LDSM) -> g_q fp32, g_k/g_v single fp16
    gemm_mma<0><<<dim3(2304 / 128, MTOT / 128), 256>>>(qkv_b, nullptr);

    // 2) tensor-core flash attention per (b, head) -> g_aoF
    attn_mma<<<BATCH * NH, ATHR, ATT_SMEM>>>(relh, relw);

    // 3) proj GEMM (1-term, LDSM) -> d_out
    gemm_mma<1><<<dim3(DIM / 128, MTOT / 128), 256>>>(proj_b, out);
}

// round 16
// speedup vs baseline: 2.4639x; 1.0265x over previous
#include <cuda_runtime.h>
#include <cuda_fp16.h>
#include <cstdint>

// ---------------- problem constants ----------------
#define BATCH   256
#define NH      12
#define HD      64
#define DIM     768          // NH*HD
#define WIN     14
#define NTOK    196          // WIN*WIN
#define NPAD    256          // padded token count for K/V tiles
#define MTOT    (BATCH*NTOK) // 50176
#define REL     27           // 2*WIN-1
#define RSTR    68           // padded rel-table row stride (floats)

// ---------------- scratch (device globals; no allocation allowed) -------
__device__ float g_q[BATCH*NH*NTOK*HD];                      // fp32, q*0.125
__device__ __half g_kF[BATCH*NH*NPAD*HD];                    // [b][h][n][d] fp16 (pad=0)
__device__ __half g_vF[BATCH*NH*HD*NPAD];                    // [b][h][d][n] fp16 (pad=0)
__device__ __half g_wqF[3*DIM*DIM];                          // qkv_w fp16
__device__ __half g_wpF[DIM*DIM];                            // proj_w fp16
__device__ __half g_aoF[MTOT*DIM];                           // attn out fp16

// =========================================================================
// helpers
// =========================================================================
__device__ __forceinline__ void mma_f16(float c[4],
                                        uint32_t a0, uint32_t a1, uint32_t a2, uint32_t a3,
                                        uint32_t b0, uint32_t b1)
{
    asm("mma.sync.aligned.m16n8k16.row.col.f32.f16.f16.f32 "
        "{%0,%1,%2,%3}, {%4,%5,%6,%7}, {%8,%9}, {%0,%1,%2,%3};"
        : "+f"(c[0]), "+f"(c[1]), "+f"(c[2]), "+f"(c[3])
        : "r"(a0), "r"(a1), "r"(a2), "r"(a3), "r"(b0), "r"(b1));
}

#define LDSM_X4(r0, r1, r2, r3, addr) \
    asm volatile("ldmatrix.sync.aligned.m8n8.x4.shared.b16 {%0,%1,%2,%3}, [%4];" \
        : "=r"(r0), "=r"(r1), "=r"(r2), "=r"(r3) : "r"(addr))

__device__ __forceinline__ uint32_t pack_f16(float x0, float x1)
{
    uint32_t h;
    asm("cvt.rn.f16x2.f32 %0, %1, %2;" : "=r"(h) : "f"(x1), "f"(x0));
    return h;
}

__device__ __forceinline__ void cp16(uint32_t dst, const void* src)
{
    asm volatile("cp.async.cg.shared.global [%0], [%1], 16;" :: "r"(dst), "l"(src));
}
#define CP_COMMIT() asm volatile("cp.async.commit_group;")
#define CP_WAIT(n)  asm volatile("cp.async.wait_group %0;" :: "n"(n))

// =========================================================================
// one-shot fp32 -> fp16 weight converts (x conversion fused into gemm<0>)
// =========================================================================
template<int WHICH>
__global__ __launch_bounds__(256) void split_kernel(const float* __restrict__ src, int n2)
{
    const int i = blockIdx.x * 256 + threadIdx.x;
    if (i >= n2) return;
    float2 v = ((const float2*)src)[i];
    uint32_t p = pack_f16(v.x, v.y);
    if (WHICH == 1) ((uint32_t*)g_wqF)[i] = p;
    else            ((uint32_t*)g_wpF)[i] = p;
}

// =========================================================================
// fp16 1-term GEMM, double-buffered smem, ONE sync per iteration, LDSM.
// MODE 0: A = x (fp32, converted in-loader), B = wq -> q/k/v scatter.
// MODE 1: A = g_aoF (fp16), B = wp -> out.
// =========================================================================
#define KSTR 40                       // fp16 smem row stride
#define TILE_BYTES (128*KSTR*2)       // 10240 B per tile

template<int MODE>
__global__ __launch_bounds__(256) void gemm_mma(const float* __restrict__ Af32,
                                                const float* __restrict__ bias,
                                                float* __restrict__ out)
{
    __shared__ __half AsF[2][128 * KSTR];
    __shared__ __half BsF[2][128 * KSTR];

    const int tid = threadIdx.x;
    const int m0  = blockIdx.y * 128;
    const int n0  = blockIdx.x * 128;

    const int w    = tid >> 5;
    const int lane = tid & 31;
    const int g    = lane >> 2;
    const int t    = lane & 3;
    const int wm   = (w >> 2) * 64;
    const int wn   = (w & 3) * 32;

    const int lr = tid >> 2;          // 0..63
    const int lc = (tid & 3) * 8;     // col (elements) 0,8,16,24
    const int ro0 = lr * KSTR + lc;

    const float*  gA32 = Af32 + (size_t)(m0 + lr) * 768 + lc;            // MODE 0
    const __half* gA16 = g_aoF + (size_t)(m0 + lr) * 768 + lc;           // MODE 1
    const __half* gB   = (MODE ? g_wpF : g_wqF) + (size_t)(n0 + lr) * 768 + lc;
    const size_t rstep = (size_t)64 * 768;

    // hoisted LDSM addresses (stage 0); +TILE_BYTES for stage 1, +32B per ks
    uint32_t a_addr[4], b_addr[2];
    {
        const uint32_t asb = (uint32_t)__cvta_generic_to_shared(AsF);
        const uint32_t bsb = (uint32_t)__cvta_generic_to_shared(BsF);
        const int ar = wm + (lane & 15);
        const int ac = (lane >> 4) * 8;
        const int br = wn + (lane & 7) + (lane >> 4) * 8;
        const int bc = ((lane >> 3) & 1) * 8;
#pragma unroll
        for (int mt = 0; mt < 4; mt++)
            a_addr[mt] = asb + ((ar + mt * 16) * KSTR + ac) * 2;
#pragma unroll
        for (int ntp = 0; ntp < 2; ntp++)
            b_addr[ntp] = bsb + ((br + ntp * 16) * KSTR + bc) * 2;
    }

    float acc[4][4][4];
#pragma unroll
    for (int i = 0; i < 4; i++)
#pragma unroll
        for (int j = 0; j < 4; j++)
#pragma unroll
            for (int r = 0; r < 4; r++) acc[i][j][r] = 0.f;

    uint4 pa[2], pb[2];
    // A prefetch: fp32->fp16 convert for MODE 0, direct for MODE 1
#define LOAD_A(k1)                                                          \
    if (MODE == 0) {                                                        \
        _Pragma("unroll")                                                   \
        for (int rr = 0; rr < 2; rr++) {                                    \
            const float* p = gA32 + (k1) + rr * rstep;                      \
            float4 f0 = *(const float4*)(p);                                \
            float4 f1 = *(const float4*)(p + 4);                            \
            pa[rr].x = pack_f16(f0.x, f0.y);                                \
            pa[rr].y = pack_f16(f0.z, f0.w);                                \
            pa[rr].z = pack_f16(f1.x, f1.y);                                \
            pa[rr].w = pack_f16(f1.z, f1.w);                                \
        }                                                                   \
    } else {                                                                \
        pa[0] = *(const uint4*)(gA16 + (k1));                               \
        pa[1] = *(const uint4*)(gA16 + (k1) + rstep);                       \
    }

    LOAD_A(0);
    pb[0] = *(const uint4*)(gB);          pb[1] = *(const uint4*)(gB + rstep);
    *(uint4*)&AsF[0][ro0]             = pa[0];
    *(uint4*)&AsF[0][ro0 + 64 * KSTR] = pa[1];
    *(uint4*)&BsF[0][ro0]             = pb[0];
    *(uint4*)&BsF[0][ro0 + 64 * KSTR] = pb[1];
    __syncthreads();

    for (int i = 0; i < 24; i++) {
        const int cur = i & 1;
        const bool more = (i + 1 < 24);

        if (more) {
            const int k1 = (i + 1) * 32;
            LOAD_A(k1);
            pb[0] = *(const uint4*)(gB + k1);          pb[1] = *(const uint4*)(gB + k1 + rstep);
        }

        const uint32_t so = cur * TILE_BYTES;
#pragma unroll
        for (int ks = 0; ks < 2; ks++) {
            const uint32_t ko = so + ks * 32;
            uint32_t a[4][4], b[4][2];
#pragma unroll
            for (int mt = 0; mt < 4; mt++)
                LDSM_X4(a[mt][0], a[mt][1], a[mt][2], a[mt][3], a_addr[mt] + ko);
            LDSM_X4(b[0][0], b[0][1], b[1][0], b[1][1], b_addr[0] + ko);
            LDSM_X4(b[2][0], b[2][1], b[3][0], b[3][1], b_addr[1] + ko);
#pragma unroll
            for (int mt = 0; mt < 4; mt++)
#pragma unroll
                for (int nt = 0; nt < 4; nt++)
                    mma_f16(acc[mt][nt], a[mt][0], a[mt][1], a[mt][2], a[mt][3],
                            b[nt][0], b[nt][1]);
        }

        if (more) {
            const int nxt = cur ^ 1;
            *(uint4*)&AsF[nxt][ro0]             = pa[0];
            *(uint4*)&AsF[nxt][ro0 + 64 * KSTR] = pa[1];
            *(uint4*)&BsF[nxt][ro0]             = pb[0];
            *(uint4*)&BsF[nxt][ro0 + 64 * KSTR] = pb[1];
        }
        __syncthreads();
    }

    // ----- epilogue -----
#pragma unroll
    for (int mt = 0; mt < 4; mt++) {
#pragma unroll
        for (int half = 0; half < 2; half++) {
            const int m = m0 + wm + mt * 16 + g + half * 8;
            if (MODE == 0) {
                const int b = m / NTOK;
                const int n = m - b * NTOK;
#pragma unroll
                for (int nt = 0; nt < 4; nt++) {
                    const int col0 = n0 + wn + nt * 8 + 2 * t;
                    float v0 = acc[mt][nt][half * 2 + 0] + bias[col0];
                    float v1 = acc[mt][nt][half * 2 + 1] + bias[col0 + 1];
                    const int which = col0 / DIM;
                    const int rem   = col0 - which * DIM;
                    const int h     = rem >> 6;
                    const int dd    = rem & 63;
                    const int bhI   = b * NH + h;
                    if (which == 0) {
                        float2 q2 = make_float2(v0 * 0.125f, v1 * 0.125f);
                        *(float2*)&g_q[((size_t)bhI * NTOK + n) * HD + dd] = q2;
                    } else if (which == 1) {
                        const size_t idx = ((size_t)bhI * NPAD + n) * HD + dd;
                        *(uint32_t*)&g_kF[idx] = pack_f16(v0, v1);
                    } else { // V transposed [d][n], fp16
                        const size_t i0 = ((size_t)bhI * HD + dd) * NPAD + n;
                        g_vF[i0]        = __float2half_rn(v0);
                        g_vF[i0 + NPAD] = __float2half_rn(v1);
                    }
                }
            } else {
#pragma unroll
                for (int nt = 0; nt < 4; nt++) {
                    const int col = n0 + wn + nt * 8 + 2 * t;
                    float2 v;
                    v.x = acc[mt][nt][half * 2 + 0] + bias[col];
                    v.y = acc[mt][nt][half * 2 + 1] + bias[col + 1];
                    *(float2*)&out[(size_t)m * DIM + col] = v;
                }
            }
        }
    }
}

// =========================================================================
// Tensor-core flash attention: all single fp16. Chunks 0-2 full (no mask),
// chunk 3 specialized to 1 n-tile (keys 192-199; 196+ masked).
// =========================================================================
#define KS_STR  72
#define KV_TILE (64*KS_STR*2)                     // 9216 B
#define KV_STAGE (2*KV_TILE)                      // 18432 B (K + V)
#define SRH_OFF 0
#define SRW_OFF (SRH_OFF + REL*RSTR*4)            // 7344
#define SBH_OFF (SRW_OFF + REL*RSTR*4)            // 14688
#define SBW_OFF (SBH_OFF + 208*14*4)              // 26336
#define SKV_OFF (SBW_OFF + 208*14*4)              // 37984
#define ATT_SMEM (SKV_OFF + 2*KV_STAGE)           // 74848 B

#define ATHR 416

__global__ __launch_bounds__(ATHR, 1) void attn_mma(const float* __restrict__ relh,
                                                    const float* __restrict__ relw)
{
    extern __shared__ char smc[];
    float* RH = (float*)(smc + SRH_OFF);
    float* RW = (float*)(smc + SRW_OFF);
    float* BH = (float*)(smc + SBH_OFF);
    float* BW = (float*)(smc + SBW_OFF);

    const int bh  = blockIdx.x;
    const int tid = threadIdx.x;
    const int w    = tid >> 5;
    const int lane = tid & 31;
    const int g    = lane >> 2;
    const int t    = lane & 3;

    const float* qg = g_q + (size_t)bh * NTOK * HD;
    const uint32_t kvbase = (uint32_t)__cvta_generic_to_shared(smc + SKV_OFF);

#define PREFETCH_CHUNK(j0, s)                                              \
    {                                                                      \
        for (int idx = tid; idx < 1024; idx += ATHR) {                     \
            const int tile = idx >> 9;                                     \
            const int r    = (idx >> 3) & 63;                              \
            const int c8   = idx & 7;                                      \
            const __half* src;                                             \
            if (tile == 0) src = g_kF + ((size_t)bh * NPAD + (j0) + r) * HD + c8 * 8; \
            else           src = g_vF + ((size_t)bh * HD + r) * NPAD + (j0) + c8 * 8; \
            cp16(kvbase + (s) * KV_STAGE + tile * KV_TILE + r * (KS_STR*2) + c8 * 16, src); \
        }                                                                  \
        CP_COMMIT();                                                       \
    }

    PREFETCH_CHUNK(0, 0);

    for (int idx = tid; idx < REL * 16; idx += ATHR) {
        const int r = idx >> 4, i4 = idx & 15;
        ((float4*)(RH + r * RSTR))[i4] = ((const float4*)relh)[idx];
        ((float4*)(RW + r * RSTR))[i4] = ((const float4*)relw)[idx];
    }
    __syncthreads();

    if (tid < NTOK) {
        float4 q4[16];
        const float4* qr = (const float4*)(qg + tid * HD);
#pragma unroll
        for (int i = 0; i < 16; i++) q4[i] = qr[i];
        const int qh = tid / WIN, qw = tid - qh * WIN;
#pragma unroll 1
        for (int kk = 0; kk < WIN; kk++) {
            const float4* rh4 = (const float4*)(RH + (qh - kk + WIN - 1) * RSTR);
            const float4* rw4 = (const float4*)(RW + (qw - kk + WIN - 1) * RSTR);
            float sh = 0.f, sw = 0.f;
#pragma unroll
            for (int i = 0; i < 16; i++) {
                float4 a = q4[i], r = rh4[i], wv = rw4[i];
                sh += a.x * r.x + a.y * r.y + a.z * r.z + a.w * r.w;
                sw += a.x * wv.x + a.y * wv.y + a.z * wv.z + a.w * wv.w;
            }
            BH[tid * WIN + kk] = sh;
            BW[tid * WIN + kk] = sw;
        }
    } else if (tid < 208) {
#pragma unroll
        for (int kk = 0; kk < WIN; kk++) {
            BH[tid * WIN + kk] = 0.f;
            BW[tid * WIN + kk] = 0.f;
        }
    }

    // Q fragments: single fp16
    const int r0 = w * 16 + g;
    const int r1 = r0 + 8;
    const int rq0 = (r0 < NTOK) ? r0 : NTOK - 1;
    const int rq1 = (r1 < NTOK) ? r1 : NTOK - 1;
    uint32_t qf[4][4];
#pragma unroll
    for (int kt = 0; kt < 4; kt++) {
        const int kc = kt * 16 + 2 * t;
        float2 v0 = *(const float2*)(qg + rq0 * HD + kc);
        float2 v1 = *(const float2*)(qg + rq1 * HD + kc);
        float2 v2 = *(const float2*)(qg + rq0 * HD + kc + 8);
        float2 v3 = *(const float2*)(qg + rq1 * HD + kc + 8);
        qf[kt][0] = pack_f16(v0.x, v0.y);
        qf[kt][1] = pack_f16(v1.x, v1.y);
        qf[kt][2] = pack_f16(v2.x, v2.y);
        qf[kt][3] = pack_f16(v3.x, v3.y);
    }

    float oacc[8][4];
#pragma unroll
    for (int j = 0; j < 8; j++)
#pragma unroll
        for (int r = 0; r < 4; r++) oacc[j][r] = 0.f;
    float lsum0 = 0.f, lsum1 = 0.f;

    // ---- chunks 0..2: full 64 keys, no masking ----
#pragma unroll 1
    for (int chunk = 0; chunk < 3; chunk++) {
        const int j0 = chunk * 64;
        const int s  = chunk & 1;
        CP_WAIT(0);
        __syncthreads();
        PREFETCH_CHUNK(j0 + 64, s ^ 1);

        const __half* KF = (const __half*)(smc + SKV_OFF + s * KV_STAGE);
        const __half* VF = KF + 64 * KS_STR;

        float sacc[8][4];
#pragma unroll
        for (int j = 0; j < 8; j++)
#pragma unroll
            for (int r = 0; r < 4; r++) sacc[j][r] = 0.f;

#pragma unroll
        for (int kt = 0; kt < 4; kt++) {
            const int kc = kt * 16 + 2 * t;
#pragma unroll
            for (int nt = 0; nt < 8; nt++) {
                const int krow = (nt * 8 + g) * KS_STR + kc;
                uint32_t k0 = *(const uint32_t*)&KF[krow];
                uint32_t k1 = *(const uint32_t*)&KF[krow + 8];
                mma_f16(sacc[nt], qf[kt][0], qf[kt][1], qf[kt][2], qf[kt][3], k0, k1);
            }
        }

#pragma unroll
        for (int nt = 0; nt < 8; nt++) {
#pragma unroll
            for (int e = 0; e < 2; e++) {
                const int c = j0 + nt * 8 + 2 * t + e;
                const int kh = c / WIN;
                const int kw = c - kh * WIN;
                float p0 = __expf(sacc[nt][e]     + BH[r0 * WIN + kh] + BW[r0 * WIN + kw]);
                float p1 = __expf(sacc[nt][2 + e] + BH[r1 * WIN + kh] + BW[r1 * WIN + kw]);
                sacc[nt][e]     = p0;
                sacc[nt][2 + e] = p1;
                lsum0 += p0;
                lsum1 += p1;
            }
        }

#pragma unroll
        for (int kt = 0; kt < 4; kt++) {
            uint32_t ph[4];
            ph[0] = pack_f16(sacc[2*kt][0],   sacc[2*kt][1]);
            ph[1] = pack_f16(sacc[2*kt][2],   sacc[2*kt][3]);
            ph[2] = pack_f16(sacc[2*kt+1][0], sacc[2*kt+1][1]);
            ph[3] = pack_f16(sacc[2*kt+1][2], sacc[2*kt+1][3]);
            const int kc = kt * 16 + 2 * t;
#pragma unroll
            for (int nt = 0; nt < 8; nt++) {
                const int vrow = (nt * 8 + g) * KS_STR + kc;
                uint32_t v0 = *(const uint32_t*)&VF[vrow];
                uint32_t v1 = *(const uint32_t*)&VF[vrow + 8];
                mma_f16(oacc[nt], ph[0], ph[1], ph[2], ph[3], v0, v1);
            }
        }
    }

    // ---- chunk 3: keys 192-199 only (1 n-tile; 196+ masked) ----
    {
        CP_WAIT(0);
        __syncthreads();
        const __half* KF = (const __half*)(smc + SKV_OFF + 1 * KV_STAGE);
        const __half* VF = KF + 64 * KS_STR;

        float s3[4] = {0.f, 0.f, 0.f, 0.f};
#pragma unroll
        for (int kt = 0; kt < 4; kt++) {
            const int kc = kt * 16 + 2 * t;
            const int krow = g * KS_STR + kc;           // nt = 0
            uint32_t k0 = *(const uint32_t*)&KF[krow];
            uint32_t k1 = *(const uint32_t*)&KF[krow + 8];
            mma_f16(s3, qf[kt][0], qf[kt][1], qf[kt][2], qf[kt][3], k0, k1);
        }

#pragma unroll
        for (int e = 0; e < 2; e++) {
            const int c = 192 + 2 * t + e;
            float p0 = 0.f, p1 = 0.f;
            if (c < NTOK) {
                const int kh = c / WIN;
                const int kw = c - kh * WIN;
                p0 = __expf(s3[e]     + BH[r0 * WIN + kh] + BW[r0 * WIN + kw]);
                p1 = __expf(s3[2 + e] + BH[r1 * WIN + kh] + BW[r1 * WIN + kw]);
            }
            s3[e]     = p0;
            s3[2 + e] = p1;
            lsum0 += p0;
            lsum1 += p1;
        }

        // PV: single k-step (keys 192-207; 200-207 zero in P)
        uint32_t ph[4];
        ph[0] = pack_f16(s3[0], s3[1]);
        ph[1] = pack_f16(s3[2], s3[3]);
        ph[2] = 0u;
        ph[3] = 0u;
        const int kc = 2 * t;                          // kt = 0
#pragma unroll
        for (int nt = 0; nt < 8; nt++) {
            const int vrow = (nt * 8 + g) * KS_STR + kc;
            uint32_t v0 = *(const uint32_t*)&VF[vrow];
            uint32_t v1 = *(const uint32_t*)&VF[vrow + 8];
            mma_f16(oacc[nt], ph[0], ph[1], ph[2], ph[3], v0, v1);
        }
    }

    lsum0 += __shfl_xor_sync(0xffffffff, lsum0, 1);
    lsum0 += __shfl_xor_sync(0xffffffff, lsum0, 2);
    lsum1 += __shfl_xor_sync(0xffffffff, lsum1, 1);
    lsum1 += __shfl_xor_sync(0xffffffff, lsum1, 2);

    const int b = bh / NH, h = bh - (bh / NH) * NH;
    const float inv0 = 1.f / lsum0;
    const float inv1 = 1.f / lsum1;
    if (r0 < NTOK) {
        const size_t off = ((size_t)b * NTOK + r0) * DIM + h * HD;
#pragma unroll
        for (int nt = 0; nt < 8; nt++)
            *(uint32_t*)&g_aoF[off + nt * 8 + 2 * t] =
                pack_f16(oacc[nt][0] * inv0, oacc[nt][1] * inv0);
    }
    if (r1 < NTOK) {
        const size_t off = ((size_t)b * NTOK + r1) * DIM + h * HD;
#pragma unroll
        for (int nt = 0; nt < 8; nt++)
            *(uint32_t*)&g_aoF[off + nt * 8 + 2 * t] =
                pack_f16(oacc[nt][2] * inv1, oacc[nt][3] * inv1);
    }
}

// =========================================================================
extern "C" void kernel_launch(void* const* d_in, const int* in_sizes, int n_in,
                              void* d_out, int out_size)
{
    const float* x      = (const float*)d_in[0];
    const float* qkv_w  = (const float*)d_in[1];
    const float* qkv_b  = (const float*)d_in[2];
    const float* relh   = (const float*)d_in[3];
    const float* relw   = (const float*)d_in[4];
    const float* proj_w = (const float*)d_in[5];
    const float* proj_b = (const float*)d_in[6];
    float* out = (float*)d_out;

    cudaFuncSetAttribute(attn_mma,
                         cudaFuncAttributeMaxDynamicSharedMemorySize, ATT_SMEM);

    // 0) weight converts only (x conversion fused into gemm<0> loader)
    {
        const int n2q = 3 * DIM * DIM / 2;
        split_kernel<1><<<(n2q + 255) / 256, 256>>>(qkv_w, n2q);
        const int n2p = DIM * DIM / 2;
        split_kernel<2><<<(n2p + 255) / 256, 256>>>(proj_w, n2p);
    }

    // 1) QKV GEMM (1-term, fused x convert) -> g_q fp32, g_k/g_v fp16
    gemm_mma<0><<<dim3(2304 / 128, MTOT / 128), 256>>>(x, qkv_b, nullptr);

    // 2) tensor-core flash attention per (b, head) -> g_aoF
    attn_mma<<<BATCH * NH, ATHR, ATT_SMEM>>>(relh, relw);

    // 3) proj GEMM (1-term) -> d_out
    gemm_mma<1><<<dim3(DIM / 128, MTOT / 128), 256>>>(nullptr, proj_b, out);
}

// round 17
// speedup vs baseline: 2.7481x; 1.1154x over previous
#include <cuda_runtime.h>
#include <cuda_fp16.h>
#include <cstdint>

// ---------------- problem constants ----------------
#define BATCH   256
#define NH      12
#define HD      64
#define DIM     768          // NH*HD
#define WIN     14
#define NTOK    196          // WIN*WIN
#define NPAD    256          // padded token count for K/V tiles
#define MTOT    (BATCH*NTOK) // 50176
#define REL     27           // 2*WIN-1

// ---------------- scratch (device globals; no allocation allowed) -------
__device__ float g_q[BATCH*NH*NTOK*HD];                      // fp32, q*0.125
__device__ __half g_kF[BATCH*NH*NPAD*HD];                    // [b][h][n][d] fp16 (pad=0)
__device__ __half g_vF[BATCH*NH*HD*NPAD];                    // [b][h][d][n] fp16 (pad=0)
__device__ __half g_wqF[3*DIM*DIM];                          // qkv_w fp16
__device__ __half g_wpF[DIM*DIM];                            // proj_w fp16
__device__ __half g_aoF[MTOT*DIM];                           // attn out fp16

// =========================================================================
// helpers
// =========================================================================
__device__ __forceinline__ void mma_f16(float c[4],
                                        uint32_t a0, uint32_t a1, uint32_t a2, uint32_t a3,
                                        uint32_t b0, uint32_t b1)
{
    asm("mma.sync.aligned.m16n8k16.row.col.f32.f16.f16.f32 "
        "{%0,%1,%2,%3}, {%4,%5,%6,%7}, {%8,%9}, {%0,%1,%2,%3};"
        : "+f"(c[0]), "+f"(c[1]), "+f"(c[2]), "+f"(c[3])
        : "r"(a0), "r"(a1), "r"(a2), "r"(a3), "r"(b0), "r"(b1));
}

#define LDSM_X4(r0, r1, r2, r3, addr) \
    asm volatile("ldmatrix.sync.aligned.m8n8.x4.shared.b16 {%0,%1,%2,%3}, [%4];" \
        : "=r"(r0), "=r"(r1), "=r"(r2), "=r"(r3) : "r"(addr))

__device__ __forceinline__ uint32_t pack_f16(float x0, float x1)
{
    uint32_t h;
    asm("cvt.rn.f16x2.f32 %0, %1, %2;" : "=r"(h) : "f"(x1), "f"(x0));
    return h;
}

__device__ __forceinline__ void cp16(uint32_t dst, const void* src)
{
    asm volatile("cp.async.cg.shared.global [%0], [%1], 16;" :: "r"(dst), "l"(src));
}
#define CP_COMMIT() asm volatile("cp.async.commit_group;")
#define CP_WAIT(n)  asm volatile("cp.async.wait_group %0;" :: "n"(n))

// =========================================================================
// one-shot fp32 -> fp16 weight converts
// =========================================================================
template<int WHICH>
__global__ __launch_bounds__(256) void split_kernel(const float* __restrict__ src, int n2)
{
    const int i = blockIdx.x * 256 + threadIdx.x;
    if (i >= n2) return;
    float2 v = ((const float2*)src)[i];
    uint32_t p = pack_f16(v.x, v.y);
    if (WHICH == 1) ((uint32_t*)g_wqF)[i] = p;
    else            ((uint32_t*)g_wpF)[i] = p;
}

// =========================================================================
// fp16 1-term GEMM (unchanged from round 16 — at structural floor).
// =========================================================================
#define KSTR 40                       // fp16 smem row stride
#define TILE_BYTES (128*KSTR*2)       // 10240 B per tile

template<int MODE>
__global__ __launch_bounds__(256) void gemm_mma(const float* __restrict__ Af32,
                                                const float* __restrict__ bias,
                                                float* __restrict__ out)
{
    __shared__ __half AsF[2][128 * KSTR];
    __shared__ __half BsF[2][128 * KSTR];

    const int tid = threadIdx.x;
    const int m0  = blockIdx.y * 128;
    const int n0  = blockIdx.x * 128;

    const int w    = tid >> 5;
    const int lane = tid & 31;
    const int g    = lane >> 2;
    const int t    = lane & 3;
    const int wm   = (w >> 2) * 64;
    const int wn   = (w & 3) * 32;

    const int lr = tid >> 2;
    const int lc = (tid & 3) * 8;
    const int ro0 = lr * KSTR + lc;

    const float*  gA32 = Af32 + (size_t)(m0 + lr) * 768 + lc;
    const __half* gA16 = g_aoF + (size_t)(m0 + lr) * 768 + lc;
    const __half* gB   = (MODE ? g_wpF : g_wqF) + (size_t)(n0 + lr) * 768 + lc;
    const size_t rstep = (size_t)64 * 768;

    uint32_t a_addr[4], b_addr[2];
    {
        const uint32_t asb = (uint32_t)__cvta_generic_to_shared(AsF);
        const uint32_t bsb = (uint32_t)__cvta_generic_to_shared(BsF);
        const int ar = wm + (lane & 15);
        const int ac = (lane >> 4) * 8;
        const int br = wn + (lane & 7) + (lane >> 4) * 8;
        const int bc = ((lane >> 3) & 1) * 8;
#pragma unroll
        for (int mt = 0; mt < 4; mt++)
            a_addr[mt] = asb + ((ar + mt * 16) * KSTR + ac) * 2;
#pragma unroll
        for (int ntp = 0; ntp < 2; ntp++)
            b_addr[ntp] = bsb + ((br + ntp * 16) * KSTR + bc) * 2;
    }

    float acc[4][4][4];
#pragma unroll
    for (int i = 0; i < 4; i++)
#pragma unroll
        for (int j = 0; j < 4; j++)
#pragma unroll
            for (int r = 0; r < 4; r++) acc[i][j][r] = 0.f;

    uint4 pa[2], pb[2];
#define LOAD_A(k1)                                                          \
    if (MODE == 0) {                                                        \
        _Pragma("unroll")                                                   \
        for (int rr = 0; rr < 2; rr++) {                                    \
            const float* p = gA32 + (k1) + rr * rstep;                      \
            float4 f0 = *(const float4*)(p);                                \
            float4 f1 = *(const float4*)(p + 4);                            \
            pa[rr].x = pack_f16(f0.x, f0.y);                                \
            pa[rr].y = pack_f16(f0.z, f0.w);                                \
            pa[rr].z = pack_f16(f1.x, f1.y);                                \
            pa[rr].w = pack_f16(f1.z, f1.w);                                \
        }                                                                   \
    } else {                                                                \
        pa[0] = *(const uint4*)(gA16 + (k1));                               \
        pa[1] = *(const uint4*)(gA16 + (k1) + rstep);                       \
    }

    LOAD_A(0);
    pb[0] = *(const uint4*)(gB);          pb[1] = *(const uint4*)(gB + rstep);
    *(uint4*)&AsF[0][ro0]             = pa[0];
    *(uint4*)&AsF[0][ro0 + 64 * KSTR] = pa[1];
    *(uint4*)&BsF[0][ro0]             = pb[0];
    *(uint4*)&BsF[0][ro0 + 64 * KSTR] = pb[1];
    __syncthreads();

    for (int i = 0; i < 24; i++) {
        const int cur = i & 1;
        const bool more = (i + 1 < 24);

        if (more) {
            const int k1 = (i + 1) * 32;
            LOAD_A(k1);
            pb[0] = *(const uint4*)(gB + k1);          pb[1] = *(const uint4*)(gB + k1 + rstep);
        }

        const uint32_t so = cur * TILE_BYTES;
#pragma unroll
        for (int ks = 0; ks < 2; ks++) {
            const uint32_t ko = so + ks * 32;
            uint32_t a[4][4], b[4][2];
#pragma unroll
            for (int mt = 0; mt < 4; mt++)
                LDSM_X4(a[mt][0], a[mt][1], a[mt][2], a[mt][3], a_addr[mt] + ko);
            LDSM_X4(b[0][0], b[0][1], b[1][0], b[1][1], b_addr[0] + ko);
            LDSM_X4(b[2][0], b[2][1], b[3][0], b[3][1], b_addr[1] + ko);
#pragma unroll
            for (int mt = 0; mt < 4; mt++)
#pragma unroll
                for (int nt = 0; nt < 4; nt++)
                    mma_f16(acc[mt][nt], a[mt][0], a[mt][1], a[mt][2], a[mt][3],
                            b[nt][0], b[nt][1]);
        }

        if (more) {
            const int nxt = cur ^ 1;
            *(uint4*)&AsF[nxt][ro0]             = pa[0];
            *(uint4*)&AsF[nxt][ro0 + 64 * KSTR] = pa[1];
            *(uint4*)&BsF[nxt][ro0]             = pb[0];
            *(uint4*)&BsF[nxt][ro0 + 64 * KSTR] = pb[1];
        }
        __syncthreads();
    }

#pragma unroll
    for (int mt = 0; mt < 4; mt++) {
#pragma unroll
        for (int half = 0; half < 2; half++) {
            const int m = m0 + wm + mt * 16 + g + half * 8;
            if (MODE == 0) {
                const int b = m / NTOK;
                const int n = m - b * NTOK;
#pragma unroll
                for (int nt = 0; nt < 4; nt++) {
                    const int col0 = n0 + wn + nt * 8 + 2 * t;
                    float v0 = acc[mt][nt][half * 2 + 0] + bias[col0];
                    float v1 = acc[mt][nt][half * 2 + 1] + bias[col0 + 1];
                    const int which = col0 / DIM;
                    const int rem   = col0 - which * DIM;
                    const int h     = rem >> 6;
                    const int dd    = rem & 63;
                    const int bhI   = b * NH + h;
                    if (which == 0) {
                        float2 q2 = make_float2(v0 * 0.125f, v1 * 0.125f);
                        *(float2*)&g_q[((size_t)bhI * NTOK + n) * HD + dd] = q2;
                    } else if (which == 1) {
                        const size_t idx = ((size_t)bhI * NPAD + n) * HD + dd;
                        *(uint32_t*)&g_kF[idx] = pack_f16(v0, v1);
                    } else {
                        const size_t i0 = ((size_t)bhI * HD + dd) * NPAD + n;
                        g_vF[i0]        = __float2half_rn(v0);
                        g_vF[i0 + NPAD] = __float2half_rn(v1);
                    }
                }
            } else {
#pragma unroll
                for (int nt = 0; nt < 4; nt++) {
                    const int col = n0 + wn + nt * 8 + 2 * t;
                    float2 v;
                    v.x = acc[mt][nt][half * 2 + 0] + bias[col];
                    v.y = acc[mt][nt][half * 2 + 1] + bias[col + 1];
                    *(float2*)&out[(size_t)m * DIM + col] = v;
                }
            }
        }
    }
}

// =========================================================================
// Tensor-core flash attention. Bias tables BH'[r,j]=q.Rh[j] computed by
// MMA (N=32 padded), lookup j = q_coord+13-k_coord at softmax time.
// =========================================================================
#define KS_STR  72
#define KV_TILE (64*KS_STR*2)                     // 9216 B
#define KV_STAGE (2*KV_TILE)                      // 18432 B
#define BSTR    34                                // bias smem row stride (floats)
#define SR16_OFF 0                                // RH16/RW16: [32][KS_STR] halves each
#define SRW16_OFF (32*KS_STR*2)                   // 4608
#define SBH_OFF  (2*32*KS_STR*2)                  // 9216: BH' [208][BSTR] fp32
#define SBW_OFF  (SBH_OFF + 208*BSTR*4)           // 37504
#define SKV_OFF  (SBW_OFF + 208*BSTR*4)           // 65792
#define ATT_SMEM (SKV_OFF + 2*KV_STAGE)           // 102656 B

#define ATHR 416

__global__ __launch_bounds__(ATHR, 1) void attn_mma(const float* __restrict__ relh,
                                                    const float* __restrict__ relw)
{
    extern __shared__ char smc[];
    __half* RH16 = (__half*)(smc + SR16_OFF);
    __half* RW16 = (__half*)(smc + SRW16_OFF);
    float* BHs = (float*)(smc + SBH_OFF);
    float* BWs = (float*)(smc + SBW_OFF);

    const int bh  = blockIdx.x;
    const int tid = threadIdx.x;
    const int w    = tid >> 5;
    const int lane = tid & 31;
    const int g    = lane >> 2;
    const int t    = lane & 3;

    const float* qg = g_q + (size_t)bh * NTOK * HD;
    const uint32_t kvbase = (uint32_t)__cvta_generic_to_shared(smc + SKV_OFF);

#define PREFETCH_CHUNK(j0, s)                                              \
    {                                                                      \
        for (int idx = tid; idx < 1024; idx += ATHR) {                     \
            const int tile = idx >> 9;                                     \
            const int r    = (idx >> 3) & 63;                              \
            const int c8   = idx & 7;                                      \
            const __half* src;                                             \
            if (tile == 0) src = g_kF + ((size_t)bh * NPAD + (j0) + r) * HD + c8 * 8; \
            else           src = g_vF + ((size_t)bh * HD + r) * NPAD + (j0) + c8 * 8; \
            cp16(kvbase + (s) * KV_STAGE + tile * KV_TILE + r * (KS_STR*2) + c8 * 16, src); \
        }                                                                  \
        CP_COMMIT();                                                       \
    }

    PREFETCH_CHUNK(0, 0);

    // stage rel tables as fp16 [32 rows][KS_STR], rows 27..31 zero
    for (int idx = tid; idx < 32 * 64; idx += ATHR) {
        const int r = idx >> 6, c = idx & 63;
        RH16[r * KS_STR + c] = __float2half_rn(r < REL ? relh[r * 64 + c] : 0.f);
        RW16[r * KS_STR + c] = __float2half_rn(r < REL ? relw[r * 64 + c] : 0.f);
    }

    // Q fragments (single fp16); pad rows clamped
    const int r0 = w * 16 + g;
    const int r1 = r0 + 8;
    const int rq0 = (r0 < NTOK) ? r0 : NTOK - 1;
    const int rq1 = (r1 < NTOK) ? r1 : NTOK - 1;
    uint32_t qf[4][4];
#pragma unroll
    for (int kt = 0; kt < 4; kt++) {
        const int kc = kt * 16 + 2 * t;
        float2 v0 = *(const float2*)(qg + rq0 * HD + kc);
        float2 v1 = *(const float2*)(qg + rq1 * HD + kc);
        float2 v2 = *(const float2*)(qg + rq0 * HD + kc + 8);
        float2 v3 = *(const float2*)(qg + rq1 * HD + kc + 8);
        qf[kt][0] = pack_f16(v0.x, v0.y);
        qf[kt][1] = pack_f16(v1.x, v1.y);
        qf[kt][2] = pack_f16(v2.x, v2.y);
        qf[kt][3] = pack_f16(v3.x, v3.y);
    }
    __syncthreads();   // RH16/RW16 ready

    // ---- bias GEMMs: BH'[208][32] = Q @ RH16^T, same for BW' ----
    {
        float bh_acc[4][4], bw_acc[4][4];
#pragma unroll
        for (int nt = 0; nt < 4; nt++)
#pragma unroll
            for (int r = 0; r < 4; r++) { bh_acc[nt][r] = 0.f; bw_acc[nt][r] = 0.f; }

#pragma unroll
        for (int kt = 0; kt < 4; kt++) {
            const int kc = kt * 16 + 2 * t;
#pragma unroll
            for (int nt = 0; nt < 4; nt++) {
                const int brow = (nt * 8 + g) * KS_STR + kc;
                uint32_t h0 = *(const uint32_t*)&RH16[brow];
                uint32_t h1 = *(const uint32_t*)&RH16[brow + 8];
                uint32_t w0 = *(const uint32_t*)&RW16[brow];
                uint32_t w1 = *(const uint32_t*)&RW16[brow + 8];
                mma_f16(bh_acc[nt], qf[kt][0], qf[kt][1], qf[kt][2], qf[kt][3], h0, h1);
                mma_f16(bw_acc[nt], qf[kt][0], qf[kt][1], qf[kt][2], qf[kt][3], w0, w1);
            }
        }
#pragma unroll
        for (int nt = 0; nt < 4; nt++) {
            const int c = nt * 8 + 2 * t;
            *(float2*)&BHs[r0 * BSTR + c] = make_float2(bh_acc[nt][0], bh_acc[nt][1]);
            *(float2*)&BHs[r1 * BSTR + c] = make_float2(bh_acc[nt][2], bh_acc[nt][3]);
            *(float2*)&BWs[r0 * BSTR + c] = make_float2(bw_acc[nt][0], bw_acc[nt][1]);
            *(float2*)&BWs[r1 * BSTR + c] = make_float2(bw_acc[nt][2], bw_acc[nt][3]);
        }
    }

    // per-thread bias lookup bases: value at pb[-k_coord]
    const int qh0 = rq0 / WIN, qw0 = rq0 - qh0 * WIN;
    const int qh1 = rq1 / WIN, qw1 = rq1 - qh1 * WIN;
    const float* pbh0 = BHs + r0 * BSTR + qh0 + 13;
    const float* pbh1 = BHs + r1 * BSTR + qh1 + 13;
    const float* pbw0 = BWs + r0 * BSTR + qw0 + 13;
    const float* pbw1 = BWs + r1 * BSTR + qw1 + 13;

    float oacc[8][4];
#pragma unroll
    for (int j = 0; j < 8; j++)
#pragma unroll
        for (int r = 0; r < 4; r++) oacc[j][r] = 0.f;
    float lsum0 = 0.f, lsum1 = 0.f;

    // ---- chunks 0..2: full 64 keys ----
#pragma unroll 1
    for (int chunk = 0; chunk < 3; chunk++) {
        const int j0 = chunk * 64;
        const int s  = chunk & 1;
        CP_WAIT(0);
        __syncthreads();    // also publishes BHs/BWs on chunk 0
        PREFETCH_CHUNK(j0 + 64, s ^ 1);

        const __half* KF = (const __half*)(smc + SKV_OFF + s * KV_STAGE);
        const __half* VF = KF + 64 * KS_STR;

        float sacc[8][4];
#pragma unroll
        for (int j = 0; j < 8; j++)
#pragma unroll
            for (int r = 0; r < 4; r++) sacc[j][r] = 0.f;

#pragma unroll
        for (int kt = 0; kt < 4; kt++) {
            const int kc = kt * 16 + 2 * t;
#pragma unroll
            for (int nt = 0; nt < 8; nt++) {
                const int krow = (nt * 8 + g) * KS_STR + kc;
                uint32_t k0 = *(const uint32_t*)&KF[krow];
                uint32_t k1 = *(const uint32_t*)&KF[krow + 8];
                mma_f16(sacc[nt], qf[kt][0], qf[kt][1], qf[kt][2], qf[kt][3], k0, k1);
            }
        }

#pragma unroll
        for (int nt = 0; nt < 8; nt++) {
#pragma unroll
            for (int e = 0; e < 2; e++) {
                const int c = j0 + nt * 8 + 2 * t + e;
                const int kh = c / WIN;
                const int kw = c - kh * WIN;
                float p0 = __expf(sacc[nt][e]     + pbh0[-kh] + pbw0[-kw]);
                float p1 = __expf(sacc[nt][2 + e] + pbh1[-kh] + pbw1[-kw]);
                sacc[nt][e]     = p0;
                sacc[nt][2 + e] = p1;
                lsum0 += p0;
                lsum1 += p1;
            }
        }

#pragma unroll
        for (int kt = 0; kt < 4; kt++) {
            uint32_t ph[4];
            ph[0] = pack_f16(sacc[2*kt][0],   sacc[2*kt][1]);
            ph[1] = pack_f16(sacc[2*kt][2],   sacc[2*kt][3]);
            ph[2] = pack_f16(sacc[2*kt+1][0], sacc[2*kt+1][1]);
            ph[3] = pack_f16(sacc[2*kt+1][2], sacc[2*kt+1][3]);
            const int kc = kt * 16 + 2 * t;
#pragma unroll
            for (int nt = 0; nt < 8; nt++) {
                const int vrow = (nt * 8 + g) * KS_STR + kc;
                uint32_t v0 = *(const uint32_t*)&VF[vrow];
                uint32_t v1 = *(const uint32_t*)&VF[vrow + 8];
                mma_f16(oacc[nt], ph[0], ph[1], ph[2], ph[3], v0, v1);
            }
        }
    }

    // ---- chunk 3: keys 192-199 only (1 n-tile; 196+ masked) ----
    {
        CP_WAIT(0);
        __syncthreads();
        const __half* KF = (const __half*)(smc + SKV_OFF + 1 * KV_STAGE);
        const __half* VF = KF + 64 * KS_STR;

        float s3[4] = {0.f, 0.f, 0.f, 0.f};
#pragma unroll
        for (int kt = 0; kt < 4; kt++) {
            const int kc = kt * 16 + 2 * t;
            const int krow = g * KS_STR + kc;
            uint32_t k0 = *(const uint32_t*)&KF[krow];
            uint32_t k1 = *(const uint32_t*)&KF[krow + 8];
            mma_f16(s3, qf[kt][0], qf[kt][1], qf[kt][2], qf[kt][3], k0, k1);
        }

#pragma unroll
        for (int e = 0; e < 2; e++) {
            const int c = 192 + 2 * t + e;
            float p0 = 0.f, p1 = 0.f;
            if (c < NTOK) {
                const int kh = c / WIN;
                const int kw = c - kh * WIN;
                p0 = __expf(s3[e]     + pbh0[-kh] + pbw0[-kw]);
                p1 = __expf(s3[2 + e] + pbh1[-kh] + pbw1[-kw]);
            }
            s3[e]     = p0;
            s3[2 + e] = p1;
            lsum0 += p0;
            lsum1 += p1;
        }

        uint32_t ph[4];
        ph[0] = pack_f16(s3[0], s3[1]);
        ph[1] = pack_f16(s3[2], s3[3]);
        ph[2] = 0u;
        ph[3] = 0u;
        const int kc = 2 * t;
#pragma unroll
        for (int nt = 0; nt < 8; nt++) {
            const int vrow = (nt * 8 + g) * KS_STR + kc;
            uint32_t v0 = *(const uint32_t*)&VF[vrow];
            uint32_t v1 = *(const uint32_t*)&VF[vrow + 8];
            mma_f16(oacc[nt], ph[0], ph[1], ph[2], ph[3], v0, v1);
        }
    }

    lsum0 += __shfl_xor_sync(0xffffffff, lsum0, 1);
    lsum0 += __shfl_xor_sync(0xffffffff, lsum0, 2);
    lsum1 += __shfl_xor_sync(0xffffffff, lsum1, 1);
    lsum1 += __shfl_xor_sync(0xffffffff, lsum1, 2);

    const int b = bh / NH, h = bh - (bh / NH) * NH;
    const float inv0 = 1.f / lsum0;
    const float inv1 = 1.f / lsum1;
    if (r0 < NTOK) {
        const size_t off = ((size_t)b * NTOK + r0) * DIM + h * HD;
#pragma unroll
        for (int nt = 0; nt < 8; nt++)
            *(uint32_t*)&g_aoF[off + nt * 8 + 2 * t] =
                pack_f16(oacc[nt][0] * inv0, oacc[nt][1] * inv0);
    }
    if (r1 < NTOK) {
        const size_t off = ((size_t)b * NTOK + r1) * DIM + h * HD;
#pragma unroll
        for (int nt = 0; nt < 8; nt++)
            *(uint32_t*)&g_aoF[off + nt * 8 + 2 * t] =
                pack_f16(oacc[nt][2] * inv1, oacc[nt][3] * inv1);
    }
}

// =========================================================================
extern "C" void kernel_launch(void* const* d_in, const int* in_sizes, int n_in,
                              void* d_out, int out_size)
{
    const float* x      = (const float*)d_in[0];
    const float* qkv_w  = (const float*)d_in[1];
    const float* qkv_b  = (const float*)d_in[2];
    const float* relh   = (const float*)d_in[3];
    const float* relw   = (const float*)d_in[4];
    const float* proj_w = (const float*)d_in[5];
    const float* proj_b = (const float*)d_in[6];
    float* out = (float*)d_out;

    cudaFuncSetAttribute(attn_mma,
                         cudaFuncAttributeMaxDynamicSharedMemorySize, ATT_SMEM);

    // 0) weight converts
    {
        const int n2q = 3 * DIM * DIM / 2;
        split_kernel<1><<<(n2q + 255) / 256, 256>>>(qkv_w, n2q);
        const int n2p = DIM * DIM / 2;
        split_kernel<2><<<(n2p + 255) / 256, 256>>>(proj_w, n2p);
    }

    // 1) QKV GEMM -> g_q fp32, g_k/g_v fp16
    gemm_mma<0><<<dim3(2304 / 128, MTOT / 128), 256>>>(x, qkv_b, nullptr);

    // 2) tensor-core flash attention -> g_aoF
    attn_mma<<<BATCH * NH, ATHR, ATT_SMEM>>>(relh, relw);

    // 3) proj GEMM -> d_out
    gemm_mma<1><<<dim3(DIM / 128, MTOT / 128), 256>>>(nullptr, proj_b, out);
}